// round 2
// baseline (speedup 1.0000x reference)
#include <cuda_runtime.h>
#include <cuda_bf16.h>
#include <cstdint>

#define NROWS 131072
#define H 128
#define NK 20
#define NSEG 8192
#define KIN 384          // 256 (x) + 128 (h)
#define GD 512           // 4*H gates
#define STEPS 11         // PRED_LEN - 1
#define XROWS_PER_BLOCK 8

// ------------------- persistent state (device globals; no allocs) -------------------
__device__ float    g_h     [(size_t)NROWS * H];
__device__ float    g_c     [(size_t)NROWS * H];
__device__ float    g_rel   [(size_t)NROWS * 2];
__device__ float    g_pos   [(size_t)NROWS * 2];
__device__ float    g_alpha [(size_t)NROWS * NK];
__device__ float    g_fd    [(size_t)NROWS * NK * 2];
__device__ unsigned g_segmax[(size_t)NSEG * H];
__device__ float    g_P     [(size_t)NSEG * H];        // relu(seg_max @ W_pool + b_pool)
__device__ float    g_xh    [(size_t)NROWS * KIN];     // [pos_emb | fld_emb | pool | h]
__device__ float    g_gates [(size_t)NROWS * GD];
__device__ float    g_W     [(size_t)KIN * GD];        // [Wx ; Wh]
__device__ float    g_bl    [GD];
__device__ unsigned char g_mask[NROWS];
__device__ int      g_fmt;                              // 1 = mask stored as int32

// ------------------- helpers -------------------
__device__ __forceinline__ unsigned enc_f(float f) {
    unsigned u = __float_as_uint(f);
    return (u & 0x80000000u) ? ~u : (u | 0x80000000u);
}
__device__ __forceinline__ float dec_f(unsigned u) {
    return (u & 0x80000000u) ? __uint_as_float(u & 0x7FFFFFFFu) : __uint_as_float(~u);
}
__device__ __forceinline__ float sigm(float x) { return 1.0f / (1.0f + expf(-x)); }

// ------------------- mask format detect + normalize -------------------
// If seq_mask was serialized as int32 (0/1), all bytes at offset %4 != 0 within
// the first 4096 bytes are zero. If serialized as 1-byte bool, ~half of them
// are 1 (P[all zero] ~ 2^-3072). Reads stay in-bounds for both layouts.
__global__ void k_mask_detect(const unsigned char* __restrict__ raw) {
    __shared__ int cnt;
    if (threadIdx.x == 0) cnt = 0;
    __syncthreads();
    int local = 0;
    for (int i = threadIdx.x; i < 4096; i += 256)
        if ((i & 3) && raw[i]) local++;
    atomicAdd(&cnt, local);
    __syncthreads();
    if (threadIdx.x == 0) g_fmt = (cnt == 0) ? 1 : 0;
}
__global__ void k_mask_norm(const unsigned char* __restrict__ raw) {
    int n = blockIdx.x * blockDim.x + threadIdx.x;
    if (n < NROWS)
        g_mask[n] = g_fmt ? (raw[(size_t)4 * n] != 0) : (raw[n] != 0);
}

// ------------------- init: build combined weight matrix -------------------
__global__ void k_init_w(const float* __restrict__ Wx, const float* __restrict__ Wh,
                         const float* __restrict__ b_lstm) {
    int idx = blockIdx.x * blockDim.x + threadIdx.x;
    int tot = KIN * GD;
    for (int i = idx; i < tot; i += gridDim.x * blockDim.x) {
        int r = i / GD, c = i % GD;
        g_W[i] = (r < 256) ? Wx[r * GD + c] : Wh[(r - 256) * GD + c];
    }
    if (idx < GD) g_bl[idx] = b_lstm[idx];
}

// ------------------- init: per-row state + pred[0] -------------------
__global__ void k_init_state(const float* __restrict__ sf, const float* __restrict__ last_pos,
                             const float* __restrict__ a0, const float* __restrict__ fd0,
                             const float* __restrict__ W_out, const float* __restrict__ b_out,
                             float* __restrict__ pred0) {
    int n = blockIdx.x, t = threadIdx.x;
    __shared__ float r0[H], r1[H];
    __shared__ float av[NK];
    float hv = sf[(size_t)n * H + t];
    g_h[(size_t)n * H + t] = hv;
    g_c[(size_t)n * H + t] = 0.0f;
    r0[t] = hv * W_out[2 * t];
    r1[t] = hv * W_out[2 * t + 1];
    if (t < NK) av[t] = a0[(size_t)n * NK + t];
    __syncthreads();
    for (int s = 64; s > 0; s >>= 1) {
        if (t < s) { r0[t] += r0[t + s]; r1[t] += r1[t + s]; }
        __syncthreads();
    }
    if (t < 2) {
        float out = (t == 0 ? r0[0] : r1[0]) + b_out[t];
        g_rel[(size_t)n * 2 + t] = out;
        g_pos[(size_t)n * 2 + t] = last_pos[(size_t)n * 2 + t] + out;
        pred0[(size_t)n * 2 + t] = out;
    }
    if (t < NK) {
        float s = 0.0f;
        #pragma unroll
        for (int k = 0; k < NK; k++) s += av[k];
        g_alpha[(size_t)n * NK + t] = av[t] / s;
    }
    if (t < 2 * NK) g_fd[(size_t)n * 2 * NK + t] = fd0[(size_t)n * 2 * NK + t];
}

// ------------------- per-step kernels -------------------
__global__ void k_seg_clear() {
    int i = blockIdx.x * blockDim.x + threadIdx.x;
    if (i < NSEG * H) g_segmax[i] = 0u;
}

__global__ void k_segmax(const int* __restrict__ seg_ids) {
    int n = blockIdx.x, t = threadIdx.x;
    int s = seg_ids[n];
    unsigned key = enc_f(g_h[(size_t)n * H + t]);
    atomicMax(&g_segmax[(size_t)s * H + t], key);
}

__global__ void k_pool(const float* __restrict__ W_pool, const float* __restrict__ b_pool) {
    int s = blockIdx.x, t = threadIdx.x;
    __shared__ float sv[H];
    sv[t] = dec_f(g_segmax[(size_t)s * H + t]);
    __syncthreads();
    float acc = b_pool[t];
    #pragma unroll 8
    for (int k = 0; k < H; k++) acc += sv[k] * W_pool[k * H + t];
    g_P[(size_t)s * H + t] = fmaxf(acc, 0.0f);
}

__global__ void k_x(const int* __restrict__ seg_ids,
                    const float* __restrict__ W_pos, const float* __restrict__ b_pos,
                    const float* __restrict__ W_fld, const float* __restrict__ b_fld) {
    __shared__ float Wf[NK * 2 * 64];   // 2560
    __shared__ float Wp[2 * 64];
    __shared__ float bp[64], bf[64];
    __shared__ float dtp[NK * 2];
    int t = threadIdx.x;
    for (int i = t; i < NK * 2 * 64; i += 128) Wf[i] = W_fld[i];
    if (t < 128) Wp[t] = W_pos[t];
    if (t < 64)  { bp[t] = b_pos[t]; bf[t] = b_fld[t]; }
    int base = blockIdx.x * XROWS_PER_BLOCK;
    for (int r = 0; r < XROWS_PER_BLOCK; r++) {
        int n = base + r;
        __syncthreads();
        if (t < 2 * NK) dtp[t] = g_alpha[(size_t)n * NK + (t >> 1)] * g_fd[(size_t)n * 2 * NK + t];
        __syncthreads();
        float rx = g_rel[(size_t)n * 2 + 0];
        float ry = g_rel[(size_t)n * 2 + 1];
        size_t xb = (size_t)n * KIN;
        if (t < 64) {
            g_xh[xb + t] = rx * Wp[t] + ry * Wp[64 + t] + bp[t];
        } else {
            int e = t - 64;
            float acc = bf[e];
            #pragma unroll
            for (int k = 0; k < 2 * NK; k++) acc += dtp[k] * Wf[k * 64 + e];
            g_xh[xb + t] = acc;
        }
        int s = seg_ids[n];
        g_xh[xb + 128 + t] = g_P[(size_t)s * H + t];
        g_xh[xb + 256 + t] = g_h[(size_t)n * H + t];
    }
}

// SGEMM: gates = [x|h](M x 384) @ g_W(384 x 512) + bias. BM=BN=128, BK=8, 8x8/thread.
__global__ void __launch_bounds__(256) k_gemm() {
    __shared__ float As[8][128];
    __shared__ float Bs[8][128];
    int t = threadIdx.x;
    int tx = t % 16, ty = t / 16;
    int row0 = blockIdx.x * 128;
    int col0 = blockIdx.y * 128;
    float acc[8][8];
    #pragma unroll
    for (int i = 0; i < 8; i++)
        #pragma unroll
        for (int j = 0; j < 8; j++) acc[i][j] = 0.0f;

    int ar = t >> 1;            // 0..127
    int ak = (t & 1) * 4;       // 0,4
    int bk = t >> 5;            // 0..7
    int bc = (t & 31) * 4;      // 0..124

    for (int k0 = 0; k0 < KIN; k0 += 8) {
        float4 a = *(const float4*)&g_xh[(size_t)(row0 + ar) * KIN + k0 + ak];
        As[ak + 0][ar] = a.x; As[ak + 1][ar] = a.y;
        As[ak + 2][ar] = a.z; As[ak + 3][ar] = a.w;
        *(float4*)&Bs[bk][bc] = *(const float4*)&g_W[(size_t)(k0 + bk) * GD + col0 + bc];
        __syncthreads();
        #pragma unroll
        for (int kk = 0; kk < 8; kk++) {
            float ra[8], rb[8];
            #pragma unroll
            for (int i = 0; i < 8; i++) ra[i] = As[kk][ty * 8 + i];
            #pragma unroll
            for (int j = 0; j < 8; j++) rb[j] = Bs[kk][tx * 8 + j];
            #pragma unroll
            for (int i = 0; i < 8; i++)
                #pragma unroll
                for (int j = 0; j < 8; j++) acc[i][j] += ra[i] * rb[j];
        }
        __syncthreads();
    }
    #pragma unroll
    for (int i = 0; i < 8; i++) {
        int r = row0 + ty * 8 + i;
        #pragma unroll
        for (int j = 0; j < 8; j++) {
            int c = col0 + tx * 8 + j;
            g_gates[(size_t)r * GD + c] = acc[i][j] + g_bl[c];
        }
    }
}

__global__ void k_lstm(const float* __restrict__ W_out, const float* __restrict__ b_out,
                       const float* __restrict__ field_A, const float* __restrict__ trans,
                       float* __restrict__ pred) {
    int n = blockIdx.x, t = threadIdx.x;
    bool m = g_mask[n] != 0;
    __shared__ float r0[H], r1[H];
    __shared__ float pos_s[2];
    __shared__ float al_s[NK], z_s[NK];

    const float* g = &g_gates[(size_t)n * GD];
    float gi = g[t], gf = g[t + 128], gg = g[t + 256], go = g[t + 384];
    float c = g_c[(size_t)n * H + t];
    float h = g_h[(size_t)n * H + t];
    float cn = sigm(gf) * c + sigm(gi) * tanhf(gg);
    float hn = sigm(go) * tanhf(cn);
    float h2 = m ? hn : h;
    float c2 = m ? cn : c;
    g_h[(size_t)n * H + t] = h2;
    g_c[(size_t)n * H + t] = c2;

    if (t < NK) al_s[t] = g_alpha[(size_t)n * NK + t];
    r0[t] = h2 * W_out[2 * t];
    r1[t] = h2 * W_out[2 * t + 1];
    __syncthreads();
    for (int s = 64; s > 0; s >>= 1) {
        if (t < s) { r0[t] += r0[t + s]; r1[t] += r1[t + s]; }
        __syncthreads();
    }
    if (t < 2) {
        float out = (t == 0 ? r0[0] : r1[0]) + b_out[t];
        float rel = m ? out : g_rel[(size_t)n * 2 + t];
        float p = g_pos[(size_t)n * 2 + t] + rel;
        g_rel[(size_t)n * 2 + t] = rel;
        g_pos[(size_t)n * 2 + t] = p;
        pred[(size_t)n * 2 + t] = rel;
        pos_s[t] = p;
    }
    if (t < NK) {
        float z = 0.0f;
        #pragma unroll
        for (int k2 = 0; k2 < NK; k2++) z += al_s[k2] * trans[k2 * NK + t];
        z_s[t] = z;
    }
    __syncthreads();
    if (t < 2 * NK && m) {
        int k = t >> 1, e = t & 1;
        g_fd[(size_t)n * 2 * NK + t] =
            pos_s[0] * field_A[k * 4 + e] + pos_s[1] * field_A[k * 4 + 2 + e];
    }
    if (t < NK && m) {
        float mx = z_s[0];
        #pragma unroll
        for (int k = 1; k < NK; k++) mx = fmaxf(mx, z_s[k]);
        float s = 0.0f;
        #pragma unroll
        for (int k = 0; k < NK; k++) s += expf(z_s[k] - mx);
        g_alpha[(size_t)n * NK + t] = expf(z_s[t] - mx) / s;
    }
}

// ------------------- launch -------------------
extern "C" void kernel_launch(void* const* d_in, const int* in_sizes, int n_in,
                              void* d_out, int out_size) {
    const float* state_final = (const float*)d_in[0];
    const float* last_pos    = (const float*)d_in[1];
    const float* alpha0      = (const float*)d_in[2];
    const float* fields_disp0= (const float*)d_in[3];
    const float* W_pos       = (const float*)d_in[4];
    const float* b_pos       = (const float*)d_in[5];
    const float* W_fld       = (const float*)d_in[6];
    const float* b_fld       = (const float*)d_in[7];
    const float* W_pool      = (const float*)d_in[8];
    const float* b_pool      = (const float*)d_in[9];
    const float* Wx          = (const float*)d_in[10];
    const float* Wh          = (const float*)d_in[11];
    const float* b_lstm      = (const float*)d_in[12];
    const float* W_out       = (const float*)d_in[13];
    const float* b_out       = (const float*)d_in[14];
    const float* field_A     = (const float*)d_in[15];
    const float* trans       = (const float*)d_in[16];
    const int*   seg_ids     = (const int*)d_in[17];
    const unsigned char* seq_mask = (const unsigned char*)d_in[18];
    float* pred = (float*)d_out;   // (12, N, 2)

    k_mask_detect<<<1, 256>>>(seq_mask);
    k_mask_norm<<<(NROWS + 255) / 256, 256>>>(seq_mask);
    k_init_w<<<256, 256>>>(Wx, Wh, b_lstm);
    k_init_state<<<NROWS, 128>>>(state_final, last_pos, alpha0, fields_disp0,
                                 W_out, b_out, pred);

    for (int step = 1; step <= STEPS; step++) {
        k_seg_clear<<<(NSEG * H + 255) / 256, 256>>>();
        k_segmax<<<NROWS, H>>>(seg_ids);
        k_pool<<<NSEG, H>>>(W_pool, b_pool);
        k_x<<<NROWS / XROWS_PER_BLOCK, 128>>>(seg_ids, W_pos, b_pos, W_fld, b_fld);
        k_gemm<<<dim3(NROWS / 128, GD / 128), 256>>>();
        k_lstm<<<NROWS, H>>>(W_out, b_out, field_A, trans,
                             pred + (size_t)step * NROWS * 2);
    }
}

// round 4
// speedup vs baseline: 1.7417x; 1.7417x over previous
#include <cuda_runtime.h>
#include <cuda_bf16.h>
#include <cstdint>

#define NROWS 131072
#define H 128
#define NK 20
#define NSEG 8192
#define KIN 384          // 256 (x) + 128 (h)
#define GD 512           // 4*H gates
#define KSPLIT 768       // [hi | lo] along K
#define STEPS 11
#define XROWS_PER_BLOCK 8

// ------------------- persistent state (device globals; no allocs) -------------------
__device__ float    g_h     [(size_t)NROWS * H];
__device__ float    g_c     [(size_t)NROWS * H];
__device__ float    g_rel   [(size_t)NROWS * 2];
__device__ float    g_pos   [(size_t)NROWS * 2];
__device__ float    g_alpha [(size_t)NROWS * NK];
__device__ float    g_fd    [(size_t)NROWS * NK * 2];
__device__ unsigned g_segmax[(size_t)NSEG * H];
__device__ float    g_P     [(size_t)NSEG * H];
__device__ __nv_bfloat16 g_xa[(size_t)NROWS * KSPLIT];   // A': [hi(384) | lo(384)] per row
__device__ __nv_bfloat16 g_Wb[(size_t)GD * KSPLIT];      // B'': [n][hi(384) | lo(384)] K-major
__device__ float    g_gates [(size_t)NROWS * GD];
__device__ float    g_bl    [GD];
__device__ unsigned char g_mask[NROWS];
__device__ int      g_fmt;

// ------------------- low-level helpers -------------------
__device__ __forceinline__ void cp16(uint32_t dst, const void* src) {
    asm volatile("cp.async.cg.shared.global [%0], [%1], 16;" :: "r"(dst), "l"(src));
}
#define CP_COMMIT() asm volatile("cp.async.commit_group;" ::: "memory")
#define CP_WAIT(n)  asm volatile("cp.async.wait_group %0;" :: "n"(n) : "memory")

__device__ __forceinline__ void ldm4(uint32_t* r, uint32_t addr) {
    asm volatile("ldmatrix.sync.aligned.m8n8.x4.shared.b16 {%0,%1,%2,%3}, [%4];"
                 : "=r"(r[0]), "=r"(r[1]), "=r"(r[2]), "=r"(r[3]) : "r"(addr));
}
__device__ __forceinline__ void mma16816(float* d, const uint32_t* a, uint32_t b0, uint32_t b1) {
    asm volatile("mma.sync.aligned.m16n8k16.row.col.f32.bf16.bf16.f32 "
                 "{%0,%1,%2,%3}, {%4,%5,%6,%7}, {%8,%9}, {%0,%1,%2,%3};"
                 : "+f"(d[0]), "+f"(d[1]), "+f"(d[2]), "+f"(d[3])
                 : "r"(a[0]), "r"(a[1]), "r"(a[2]), "r"(a[3]), "r"(b0), "r"(b1));
}

__device__ __forceinline__ unsigned enc_f(float f) {
    unsigned u = __float_as_uint(f);
    return (u & 0x80000000u) ? ~u : (u | 0x80000000u);
}
__device__ __forceinline__ float dec_f(unsigned u) {
    return (u & 0x80000000u) ? __uint_as_float(u & 0x7FFFFFFFu) : __uint_as_float(~u);
}
__device__ __forceinline__ float sigm(float x) { return 1.0f / (1.0f + expf(-x)); }

__device__ __forceinline__ void store_split(size_t n, int col, float v) {
    __nv_bfloat16 hi = __float2bfloat16(v);
    g_xa[n * KSPLIT + col] = hi;
    g_xa[n * KSPLIT + 384 + col] = __float2bfloat16(v - __bfloat162float(hi));
}

// ------------------- mask format detect + normalize -------------------
__global__ void k_mask_detect(const unsigned char* __restrict__ raw) {
    __shared__ int cnt;
    if (threadIdx.x == 0) cnt = 0;
    __syncthreads();
    int local = 0;
    for (int i = threadIdx.x; i < 4096; i += 256)
        if ((i & 3) && raw[i]) local++;
    atomicAdd(&cnt, local);
    __syncthreads();
    if (threadIdx.x == 0) g_fmt = (cnt == 0) ? 1 : 0;
}
__global__ void k_mask_norm(const unsigned char* __restrict__ raw) {
    int n = blockIdx.x * blockDim.x + threadIdx.x;
    if (n < NROWS)
        g_mask[n] = g_fmt ? (raw[(size_t)4 * n] != 0) : (raw[n] != 0);
}

// ------------------- init: B'' bf16 split [512 x 768] K-major + bias -------------------
__global__ void k_init_w(const float* __restrict__ Wx, const float* __restrict__ Wh,
                         const float* __restrict__ b_lstm) {
    int idx = blockIdx.x * blockDim.x + threadIdx.x;
    int tot = GD * KIN;
    for (int i = idx; i < tot; i += gridDim.x * blockDim.x) {
        int n = i / KIN, k = i % KIN;
        float w = (k < 256) ? Wx[(size_t)k * GD + n] : Wh[(size_t)(k - 256) * GD + n];
        __nv_bfloat16 hi = __float2bfloat16(w);
        g_Wb[(size_t)n * KSPLIT + k] = hi;
        g_Wb[(size_t)n * KSPLIT + 384 + k] = __float2bfloat16(w - __bfloat162float(hi));
    }
    if (idx < GD) g_bl[idx] = b_lstm[idx];
}

// ------------------- init: per-row state + pred[0] -------------------
__global__ void k_init_state(const float* __restrict__ sf, const float* __restrict__ last_pos,
                             const float* __restrict__ a0, const float* __restrict__ fd0,
                             const float* __restrict__ W_out, const float* __restrict__ b_out,
                             float* __restrict__ pred0) {
    int n = blockIdx.x, t = threadIdx.x;
    __shared__ float r0[H], r1[H];
    __shared__ float av[NK];
    float hv = sf[(size_t)n * H + t];
    g_h[(size_t)n * H + t] = hv;
    g_c[(size_t)n * H + t] = 0.0f;
    r0[t] = hv * W_out[2 * t];
    r1[t] = hv * W_out[2 * t + 1];
    if (t < NK) av[t] = a0[(size_t)n * NK + t];
    __syncthreads();
    for (int s = 64; s > 0; s >>= 1) {
        if (t < s) { r0[t] += r0[t + s]; r1[t] += r1[t + s]; }
        __syncthreads();
    }
    if (t < 2) {
        float out = (t == 0 ? r0[0] : r1[0]) + b_out[t];
        g_rel[(size_t)n * 2 + t] = out;
        g_pos[(size_t)n * 2 + t] = last_pos[(size_t)n * 2 + t] + out;
        pred0[(size_t)n * 2 + t] = out;
    }
    if (t < NK) {
        float s = 0.0f;
        #pragma unroll
        for (int k = 0; k < NK; k++) s += av[k];
        g_alpha[(size_t)n * NK + t] = av[t] / s;
    }
    if (t < 2 * NK) g_fd[(size_t)n * 2 * NK + t] = fd0[(size_t)n * 2 * NK + t];
}

// ------------------- per-step kernels -------------------
__global__ void k_seg_clear() {
    int i = blockIdx.x * blockDim.x + threadIdx.x;
    if (i < NSEG * H) g_segmax[i] = 0u;
}

__global__ void k_segmax(const int* __restrict__ seg_ids) {
    int n = blockIdx.x, t = threadIdx.x;
    int s = seg_ids[n];
    unsigned key = enc_f(g_h[(size_t)n * H + t]);
    atomicMax(&g_segmax[(size_t)s * H + t], key);
}

__global__ void k_pool(const float* __restrict__ W_pool, const float* __restrict__ b_pool) {
    int s = blockIdx.x, t = threadIdx.x;
    __shared__ float sv[H];
    sv[t] = dec_f(g_segmax[(size_t)s * H + t]);
    __syncthreads();
    float acc = b_pool[t];
    #pragma unroll 8
    for (int k = 0; k < H; k++) acc += sv[k] * W_pool[k * H + t];
    g_P[(size_t)s * H + t] = fmaxf(acc, 0.0f);
}

__global__ void k_x(const int* __restrict__ seg_ids,
                    const float* __restrict__ W_pos, const float* __restrict__ b_pos,
                    const float* __restrict__ W_fld, const float* __restrict__ b_fld) {
    __shared__ float Wf[NK * 2 * 64];
    __shared__ float Wp[2 * 64];
    __shared__ float bp[64], bf[64];
    __shared__ float dtp[NK * 2];
    int t = threadIdx.x;
    for (int i = t; i < NK * 2 * 64; i += 128) Wf[i] = W_fld[i];
    if (t < 128) Wp[t] = W_pos[t];
    if (t < 64)  { bp[t] = b_pos[t]; bf[t] = b_fld[t]; }
    int base = blockIdx.x * XROWS_PER_BLOCK;
    for (int r = 0; r < XROWS_PER_BLOCK; r++) {
        int n = base + r;
        __syncthreads();
        if (t < 2 * NK) dtp[t] = g_alpha[(size_t)n * NK + (t >> 1)] * g_fd[(size_t)n * 2 * NK + t];
        __syncthreads();
        float rx = g_rel[(size_t)n * 2 + 0];
        float ry = g_rel[(size_t)n * 2 + 1];
        float ev;
        if (t < 64) {
            ev = rx * Wp[t] + ry * Wp[64 + t] + bp[t];
        } else {
            int e = t - 64;
            float acc = bf[e];
            #pragma unroll
            for (int k = 0; k < 2 * NK; k++) acc += dtp[k] * Wf[k * 64 + e];
            ev = acc;
        }
        store_split((size_t)n, t, ev);
        int s = seg_ids[n];
        store_split((size_t)n, 128 + t, g_P[(size_t)s * H + t]);
        store_split((size_t)n, 256 + t, g_h[(size_t)n * H + t]);
    }
}

// ------------------- mma.sync bf16 GEMM: gates = A'' x B''^T + bias -------------------
// CTA 128x128, 8 warps (4m x 2n), warp tile 32x64, BK=32.
// K-loop = 3 split-terms x 12 k-tiles: A_hi*B_hi + A_hi*B_lo + A_lo*B_hi.
#define NKT 36
#define SPAD 40    // 32 + 8 bf16 pad: 80B row stride, conflict-free ldmatrix

__global__ void __launch_bounds__(256) k_gemm() {
    __shared__ __nv_bfloat16 As[2][128][SPAD];
    __shared__ __nv_bfloat16 Bs[2][128][SPAD];
    __shared__ float s_bias[128];

    int t = threadIdx.x;
    int lane = t & 31, warp = t >> 5;
    int wm = warp & 3, wn = warp >> 2;
    int row0 = blockIdx.x * 128, col0 = blockIdx.y * 128;

    if (t < 128) s_bias[t] = g_bl[col0 + t];

    float acc[2][8][4];
    #pragma unroll
    for (int i = 0; i < 2; i++)
        #pragma unroll
        for (int j = 0; j < 8; j++)
            #pragma unroll
            for (int k = 0; k < 4; k++) acc[i][j][k] = 0.0f;

    int lr = t >> 2, lc = (t & 3) * 8;          // load row (0..63), chunk col
    // issue loads for iteration `it` into buffer `buf`
    auto issue = [&](int it, int buf) {
        int term = it / 12, kt = it % 12;
        int a_off = (term == 2) ? 384 : 0;
        int b_off = (term == 1) ? 384 : 0;
        int acol = a_off + kt * 32 + lc;
        int bcol = b_off + kt * 32 + lc;
        #pragma unroll
        for (int i = 0; i < 2; i++) {
            int r = lr + i * 64;
            cp16((uint32_t)__cvta_generic_to_shared(&As[buf][r][lc]),
                 &g_xa[(size_t)(row0 + r) * KSPLIT + acol]);
            cp16((uint32_t)__cvta_generic_to_shared(&Bs[buf][r][lc]),
                 &g_Wb[(size_t)(col0 + r) * KSPLIT + bcol]);
        }
        CP_COMMIT();
    };

    issue(0, 0);
    for (int it = 0; it < NKT; it++) {
        int buf = it & 1;
        if (it + 1 < NKT) { issue(it + 1, buf ^ 1); CP_WAIT(1); }
        else              { CP_WAIT(0); }
        __syncthreads();

        #pragma unroll
        for (int kh = 0; kh < 2; kh++) {
            uint32_t af[2][4];
            #pragma unroll
            for (int mt = 0; mt < 2; mt++) {
                int r = wm * 32 + mt * 16 + (lane & 15);
                int c = kh * 16 + (lane >> 4) * 8;
                ldm4(af[mt], (uint32_t)__cvta_generic_to_shared(&As[buf][r][c]));
            }
            uint32_t bfr[4][4];
            #pragma unroll
            for (int nt = 0; nt < 4; nt++) {
                int r = wn * 64 + nt * 16 + (lane & 7) + ((lane >> 4) & 1) * 8;
                int c = kh * 16 + ((lane >> 3) & 1) * 8;
                ldm4(bfr[nt], (uint32_t)__cvta_generic_to_shared(&Bs[buf][r][c]));
            }
            #pragma unroll
            for (int mt = 0; mt < 2; mt++)
                #pragma unroll
                for (int nt = 0; nt < 4; nt++) {
                    mma16816(acc[mt][nt * 2],     af[mt], bfr[nt][0], bfr[nt][1]);
                    mma16816(acc[mt][nt * 2 + 1], af[mt], bfr[nt][2], bfr[nt][3]);
                }
        }
        __syncthreads();
    }

    // epilogue: bias + store fp32 gates
    #pragma unroll
    for (int mt = 0; mt < 2; mt++) {
        int r = row0 + wm * 32 + mt * 16 + (lane >> 2);
        #pragma unroll
        for (int nt = 0; nt < 8; nt++) {
            int cl = wn * 64 + nt * 8 + (lane & 3) * 2;
            float b0 = s_bias[cl], b1 = s_bias[cl + 1];
            float2 v0 = make_float2(acc[mt][nt][0] + b0, acc[mt][nt][1] + b1);
            float2 v1 = make_float2(acc[mt][nt][2] + b0, acc[mt][nt][3] + b1);
            *(float2*)&g_gates[(size_t)r * GD + col0 + cl] = v0;
            *(float2*)&g_gates[(size_t)(r + 8) * GD + col0 + cl] = v1;
        }
    }
}

// ------------------- LSTM pointwise + trajectory update -------------------
__global__ void k_lstm(const float* __restrict__ W_out, const float* __restrict__ b_out,
                       const float* __restrict__ field_A, const float* __restrict__ trans,
                       float* __restrict__ pred) {
    int n = blockIdx.x, t = threadIdx.x;
    bool m = g_mask[n] != 0;
    __shared__ float r0[H], r1[H];
    __shared__ float pos_s[2];
    __shared__ float al_s[NK], z_s[NK];

    const float* g = &g_gates[(size_t)n * GD];
    float gi = g[t], gf = g[t + 128], gg = g[t + 256], go = g[t + 384];
    float c = g_c[(size_t)n * H + t];
    float h = g_h[(size_t)n * H + t];
    float cn = sigm(gf) * c + sigm(gi) * tanhf(gg);
    float hn = sigm(go) * tanhf(cn);
    float h2 = m ? hn : h;
    float c2 = m ? cn : c;
    g_h[(size_t)n * H + t] = h2;
    g_c[(size_t)n * H + t] = c2;

    if (t < NK) al_s[t] = g_alpha[(size_t)n * NK + t];
    r0[t] = h2 * W_out[2 * t];
    r1[t] = h2 * W_out[2 * t + 1];
    __syncthreads();
    for (int s = 64; s > 0; s >>= 1) {
        if (t < s) { r0[t] += r0[t + s]; r1[t] += r1[t + s]; }
        __syncthreads();
    }
    if (t < 2) {
        float out = (t == 0 ? r0[0] : r1[0]) + b_out[t];
        float rel = m ? out : g_rel[(size_t)n * 2 + t];
        float p = g_pos[(size_t)n * 2 + t] + rel;
        g_rel[(size_t)n * 2 + t] = rel;
        g_pos[(size_t)n * 2 + t] = p;
        pred[(size_t)n * 2 + t] = rel;
        pos_s[t] = p;
    }
    if (t < NK) {
        float z = 0.0f;
        #pragma unroll
        for (int k2 = 0; k2 < NK; k2++) z += al_s[k2] * trans[k2 * NK + t];
        z_s[t] = z;
    }
    __syncthreads();
    if (t < 2 * NK && m) {
        int k = t >> 1, e = t & 1;
        g_fd[(size_t)n * 2 * NK + t] =
            pos_s[0] * field_A[k * 4 + e] + pos_s[1] * field_A[k * 4 + 2 + e];
    }
    if (t < NK && m) {
        float mx = z_s[0];
        #pragma unroll
        for (int k = 1; k < NK; k++) mx = fmaxf(mx, z_s[k]);
        float s = 0.0f;
        #pragma unroll
        for (int k = 0; k < NK; k++) s += expf(z_s[k] - mx);
        g_alpha[(size_t)n * NK + t] = expf(z_s[t] - mx) / s;
    }
}

// ------------------- launch -------------------
extern "C" void kernel_launch(void* const* d_in, const int* in_sizes, int n_in,
                              void* d_out, int out_size) {
    const float* state_final = (const float*)d_in[0];
    const float* last_pos    = (const float*)d_in[1];
    const float* alpha0      = (const float*)d_in[2];
    const float* fields_disp0= (const float*)d_in[3];
    const float* W_pos       = (const float*)d_in[4];
    const float* b_pos       = (const float*)d_in[5];
    const float* W_fld       = (const float*)d_in[6];
    const float* b_fld       = (const float*)d_in[7];
    const float* W_pool      = (const float*)d_in[8];
    const float* b_pool      = (const float*)d_in[9];
    const float* Wx          = (const float*)d_in[10];
    const float* Wh          = (const float*)d_in[11];
    const float* b_lstm      = (const float*)d_in[12];
    const float* W_out       = (const float*)d_in[13];
    const float* b_out       = (const float*)d_in[14];
    const float* field_A     = (const float*)d_in[15];
    const float* trans       = (const float*)d_in[16];
    const int*   seg_ids     = (const int*)d_in[17];
    const unsigned char* seq_mask = (const unsigned char*)d_in[18];
    float* pred = (float*)d_out;   // (12, N, 2)

    k_mask_detect<<<1, 256>>>(seq_mask);
    k_mask_norm<<<(NROWS + 255) / 256, 256>>>(seq_mask);
    k_init_w<<<256, 256>>>(Wx, Wh, b_lstm);
    k_init_state<<<NROWS, 128>>>(state_final, last_pos, alpha0, fields_disp0,
                                 W_out, b_out, pred);

    for (int step = 1; step <= STEPS; step++) {
        k_seg_clear<<<(NSEG * H + 255) / 256, 256>>>();
        k_segmax<<<NROWS, H>>>(seg_ids);
        k_pool<<<NSEG, H>>>(W_pool, b_pool);
        k_x<<<NROWS / XROWS_PER_BLOCK, 128>>>(seg_ids, W_pos, b_pos, W_fld, b_fld);
        k_gemm<<<dim3(NROWS / 128, GD / 128), 256>>>();
        k_lstm<<<NROWS, H>>>(W_out, b_out, field_A, trans,
                             pred + (size_t)step * NROWS * 2);
    }
}

// round 5
// speedup vs baseline: 1.8234x; 1.0469x over previous
#include <cuda_runtime.h>
#include <cuda_bf16.h>
#include <cstdint>

#define NROWS 131072
#define H 128
#define NK 20
#define NSEG 8192
#define KIN 384          // 256 (x) + 128 (h)
#define GD 512           // 4*H gates
#define KSPLIT 768       // [hi | lo] along K
#define STEPS 11
#define XROWS_PER_BLOCK 8

// ------------------- persistent state (device globals; no allocs) -------------------
__device__ float    g_h     [(size_t)NROWS * H];
__device__ float    g_c     [(size_t)NROWS * H];
__device__ float    g_rel   [(size_t)NROWS * 2];
__device__ float    g_pos   [(size_t)NROWS * 2];
__device__ float    g_alpha [(size_t)NROWS * NK];
__device__ float    g_fd    [(size_t)NROWS * NK * 2];
__device__ unsigned g_segmax[(size_t)NSEG * H];
__device__ float    g_P     [(size_t)NSEG * H];
__device__ __nv_bfloat16 g_xa[(size_t)NROWS * KSPLIT];   // A': [hi(384) | lo(384)] per row
__device__ __nv_bfloat16 g_Wb[(size_t)GD * KSPLIT];      // B'': [n][hi(384) | lo(384)] K-major
__device__ float    g_gates [(size_t)NROWS * GD];
__device__ float    g_bl    [GD];
__device__ unsigned char g_mask[NROWS];
__device__ int      g_fmt;

// ------------------- low-level helpers -------------------
__device__ __forceinline__ void cp16(uint32_t dst, const void* src) {
    asm volatile("cp.async.cg.shared.global [%0], [%1], 16;" :: "r"(dst), "l"(src));
}
#define CP_COMMIT() asm volatile("cp.async.commit_group;" ::: "memory")
#define CP_WAIT(n)  asm volatile("cp.async.wait_group %0;" :: "n"(n) : "memory")

__device__ __forceinline__ void ldm4(uint32_t* r, uint32_t addr) {
    asm volatile("ldmatrix.sync.aligned.m8n8.x4.shared.b16 {%0,%1,%2,%3}, [%4];"
                 : "=r"(r[0]), "=r"(r[1]), "=r"(r[2]), "=r"(r[3]) : "r"(addr));
}
__device__ __forceinline__ void mma16816(float* d, const uint32_t* a, uint32_t b0, uint32_t b1) {
    asm volatile("mma.sync.aligned.m16n8k16.row.col.f32.bf16.bf16.f32 "
                 "{%0,%1,%2,%3}, {%4,%5,%6,%7}, {%8,%9}, {%0,%1,%2,%3};"
                 : "+f"(d[0]), "+f"(d[1]), "+f"(d[2]), "+f"(d[3])
                 : "r"(a[0]), "r"(a[1]), "r"(a[2]), "r"(a[3]), "r"(b0), "r"(b1));
}

__device__ __forceinline__ unsigned enc_f(float f) {
    unsigned u = __float_as_uint(f);
    return (u & 0x80000000u) ? ~u : (u | 0x80000000u);
}
__device__ __forceinline__ float dec_f(unsigned u) {
    return (u & 0x80000000u) ? __uint_as_float(u & 0x7FFFFFFFu) : __uint_as_float(~u);
}
__device__ __forceinline__ float sigm(float x) { return 1.0f / (1.0f + expf(-x)); }

__device__ __forceinline__ void store_split(size_t n, int col, float v) {
    __nv_bfloat16 hi = __float2bfloat16(v);
    g_xa[n * KSPLIT + col] = hi;
    g_xa[n * KSPLIT + 384 + col] = __float2bfloat16(v - __bfloat162float(hi));
}

// ------------------- mask format detect + normalize -------------------
__global__ void k_mask_detect(const unsigned char* __restrict__ raw) {
    __shared__ int cnt;
    if (threadIdx.x == 0) cnt = 0;
    __syncthreads();
    int local = 0;
    for (int i = threadIdx.x; i < 4096; i += 256)
        if ((i & 3) && raw[i]) local++;
    atomicAdd(&cnt, local);
    __syncthreads();
    if (threadIdx.x == 0) g_fmt = (cnt == 0) ? 1 : 0;
}
__global__ void k_mask_norm(const unsigned char* __restrict__ raw) {
    int n = blockIdx.x * blockDim.x + threadIdx.x;
    if (n < NROWS)
        g_mask[n] = g_fmt ? (raw[(size_t)4 * n] != 0) : (raw[n] != 0);
}

// ------------------- init: B'' bf16 split [512 x 768] K-major + bias -------------------
__global__ void k_init_w(const float* __restrict__ Wx, const float* __restrict__ Wh,
                         const float* __restrict__ b_lstm) {
    int idx = blockIdx.x * blockDim.x + threadIdx.x;
    int tot = GD * KIN;
    for (int i = idx; i < tot; i += gridDim.x * blockDim.x) {
        int n = i / KIN, k = i % KIN;
        float w = (k < 256) ? Wx[(size_t)k * GD + n] : Wh[(size_t)(k - 256) * GD + n];
        __nv_bfloat16 hi = __float2bfloat16(w);
        g_Wb[(size_t)n * KSPLIT + k] = hi;
        g_Wb[(size_t)n * KSPLIT + 384 + k] = __float2bfloat16(w - __bfloat162float(hi));
    }
    if (idx < GD) g_bl[idx] = b_lstm[idx];
}

// ------------------- init: per-row state + pred[0] -------------------
__global__ void k_init_state(const float* __restrict__ sf, const float* __restrict__ last_pos,
                             const float* __restrict__ a0, const float* __restrict__ fd0,
                             const float* __restrict__ W_out, const float* __restrict__ b_out,
                             float* __restrict__ pred0) {
    int n = blockIdx.x, t = threadIdx.x;
    __shared__ float r0[H], r1[H];
    __shared__ float av[NK];
    float hv = sf[(size_t)n * H + t];
    g_h[(size_t)n * H + t] = hv;
    g_c[(size_t)n * H + t] = 0.0f;
    r0[t] = hv * W_out[2 * t];
    r1[t] = hv * W_out[2 * t + 1];
    if (t < NK) av[t] = a0[(size_t)n * NK + t];
    __syncthreads();
    for (int s = 64; s > 0; s >>= 1) {
        if (t < s) { r0[t] += r0[t + s]; r1[t] += r1[t + s]; }
        __syncthreads();
    }
    if (t < 2) {
        float out = (t == 0 ? r0[0] : r1[0]) + b_out[t];
        g_rel[(size_t)n * 2 + t] = out;
        g_pos[(size_t)n * 2 + t] = last_pos[(size_t)n * 2 + t] + out;
        pred0[(size_t)n * 2 + t] = out;
    }
    if (t < NK) {
        float s = 0.0f;
        #pragma unroll
        for (int k = 0; k < NK; k++) s += av[k];
        g_alpha[(size_t)n * NK + t] = av[t] / s;
    }
    if (t < 2 * NK) g_fd[(size_t)n * 2 * NK + t] = fd0[(size_t)n * 2 * NK + t];
}

// ------------------- per-step kernels -------------------
__global__ void k_seg_clear() {
    int i = blockIdx.x * blockDim.x + threadIdx.x;
    if (i < NSEG * H) g_segmax[i] = 0u;
}

// segment_ids sorted -> block scans 16 consecutive rows, flushes atomics only at
// segment boundaries (avg ~1 per block) instead of one atomic per row.
#define SEG_R 16
__global__ void k_segmax(const int* __restrict__ seg_ids) {
    int t = threadIdx.x;
    int r0 = blockIdx.x * SEG_R;
    __shared__ int sid[SEG_R];
    if (t < SEG_R) sid[t] = seg_ids[r0 + t];
    __syncthreads();
    int cur = sid[0];
    unsigned mx = 0u;
    #pragma unroll
    for (int r = 0; r < SEG_R; r++) {
        int s = sid[r];
        if (s != cur) {
            atomicMax(&g_segmax[(size_t)cur * H + t], mx);
            cur = s; mx = 0u;
        }
        unsigned key = enc_f(g_h[(size_t)(r0 + r) * H + t]);
        mx = mx > key ? mx : key;
    }
    atomicMax(&g_segmax[(size_t)cur * H + t], mx);
}

// W_pool cached in smem; 32 segments per block (256 blocks instead of 8192).
#define POOL_SEGS 32
__global__ void __launch_bounds__(256) k_pool(const float* __restrict__ W_pool,
                                              const float* __restrict__ b_pool) {
    extern __shared__ float psm[];           // [H*H] W_pool + [2*H] sv
    float* sv = psm + H * H;
    int t = threadIdx.x;
    for (int i = t; i < H * H; i += 256) psm[i] = W_pool[i];
    int s0 = blockIdx.x * POOL_SEGS;
    int half = t >> 7, col = t & 127;
    float b = b_pool[col];
    __syncthreads();
    for (int p = 0; p < POOL_SEGS; p += 2) {
        int s = s0 + p + half;
        sv[t] = dec_f(g_segmax[(size_t)s * H + col]);
        __syncthreads();
        float acc = b;
        #pragma unroll 8
        for (int k = 0; k < H; k++) acc += sv[half * H + k] * psm[k * H + col];
        g_P[(size_t)s * H + col] = fmaxf(acc, 0.0f);
        __syncthreads();
    }
}

__global__ void k_x(const int* __restrict__ seg_ids,
                    const float* __restrict__ W_pos, const float* __restrict__ b_pos,
                    const float* __restrict__ W_fld, const float* __restrict__ b_fld) {
    __shared__ float Wf[NK * 2 * 64];
    __shared__ float Wp[2 * 64];
    __shared__ float bp[64], bf[64];
    __shared__ float dtp[NK * 2];
    int t = threadIdx.x;
    for (int i = t; i < NK * 2 * 64; i += 128) Wf[i] = W_fld[i];
    if (t < 128) Wp[t] = W_pos[t];
    if (t < 64)  { bp[t] = b_pos[t]; bf[t] = b_fld[t]; }
    int base = blockIdx.x * XROWS_PER_BLOCK;
    for (int r = 0; r < XROWS_PER_BLOCK; r++) {
        int n = base + r;
        __syncthreads();
        if (t < 2 * NK) dtp[t] = g_alpha[(size_t)n * NK + (t >> 1)] * g_fd[(size_t)n * 2 * NK + t];
        __syncthreads();
        float rx = g_rel[(size_t)n * 2 + 0];
        float ry = g_rel[(size_t)n * 2 + 1];
        float ev;
        if (t < 64) {
            ev = rx * Wp[t] + ry * Wp[64 + t] + bp[t];
        } else {
            int e = t - 64;
            float acc = bf[e];
            #pragma unroll
            for (int k = 0; k < 2 * NK; k++) acc += dtp[k] * Wf[k * 64 + e];
            ev = acc;
        }
        store_split((size_t)n, t, ev);
        int s = seg_ids[n];
        store_split((size_t)n, 128 + t, g_P[(size_t)s * H + t]);
        store_split((size_t)n, 256 + t, g_h[(size_t)n * H + t]);
    }
}

// ------------------- mma.sync bf16 GEMM: gates = A'' x B''^T + bias -------------------
// CTA 128x128, 8 warps (4m x 2n), BK=32, 3-stage cp.async, one sync per k-iter.
// Grid (col=4, row=1024): adjacent blocks share the A row-tile -> A from L2.
// K-loop = 3 split-terms x 12 k-tiles: A_hi*B_hi + A_hi*B_lo + A_lo*B_hi.
#define NKT 36
#define SPAD 40    // 32 + 8 bf16 pad: 80B row stride, conflict-free ldmatrix
#define GSTAGES 3
#define GEMM_SMEM (2 * GSTAGES * 128 * SPAD * 2 + 512)

__global__ void __launch_bounds__(256) k_gemm() {
    extern __shared__ __nv_bfloat16 gsm[];
    __nv_bfloat16 (*As)[128][SPAD] = (__nv_bfloat16 (*)[128][SPAD])gsm;
    __nv_bfloat16 (*Bs)[128][SPAD] = (__nv_bfloat16 (*)[128][SPAD])(gsm + GSTAGES * 128 * SPAD);
    float* s_bias = (float*)(gsm + 2 * GSTAGES * 128 * SPAD);

    int t = threadIdx.x;
    int lane = t & 31, warp = t >> 5;
    int wm = warp & 3, wn = warp >> 2;
    int col0 = blockIdx.x * 128, row0 = blockIdx.y * 128;

    if (t < 128) s_bias[t] = g_bl[col0 + t];

    float acc[2][8][4];
    #pragma unroll
    for (int i = 0; i < 2; i++)
        #pragma unroll
        for (int j = 0; j < 8; j++)
            #pragma unroll
            for (int k = 0; k < 4; k++) acc[i][j][k] = 0.0f;

    int lr = t >> 2, lc = (t & 3) * 8;
    auto issue = [&](int it, int buf) {
        int term = it / 12, kt = it % 12;
        int a_off = (term == 2) ? 384 : 0;
        int b_off = (term == 1) ? 384 : 0;
        int acol = a_off + kt * 32 + lc;
        int bcol = b_off + kt * 32 + lc;
        #pragma unroll
        for (int i = 0; i < 2; i++) {
            int r = lr + i * 64;
            cp16((uint32_t)__cvta_generic_to_shared(&As[buf][r][lc]),
                 &g_xa[(size_t)(row0 + r) * KSPLIT + acol]);
            cp16((uint32_t)__cvta_generic_to_shared(&Bs[buf][r][lc]),
                 &g_Wb[(size_t)(col0 + r) * KSPLIT + bcol]);
        }
        CP_COMMIT();
    };

    issue(0, 0);
    issue(1, 1);
    for (int it = 0; it < NKT; it++) {
        int buf = it % GSTAGES;
        CP_WAIT(1);
        __syncthreads();
        if (it + 2 < NKT) issue(it + 2, (it + 2) % GSTAGES);

        #pragma unroll
        for (int kh = 0; kh < 2; kh++) {
            uint32_t af[2][4];
            #pragma unroll
            for (int mt = 0; mt < 2; mt++) {
                int r = wm * 32 + mt * 16 + (lane & 15);
                int c = kh * 16 + (lane >> 4) * 8;
                ldm4(af[mt], (uint32_t)__cvta_generic_to_shared(&As[buf][r][c]));
            }
            uint32_t bfr[4][4];
            #pragma unroll
            for (int nt = 0; nt < 4; nt++) {
                int r = wn * 64 + nt * 16 + (lane & 7) + ((lane >> 4) & 1) * 8;
                int c = kh * 16 + ((lane >> 3) & 1) * 8;
                ldm4(bfr[nt], (uint32_t)__cvta_generic_to_shared(&Bs[buf][r][c]));
            }
            #pragma unroll
            for (int mt = 0; mt < 2; mt++)
                #pragma unroll
                for (int nt = 0; nt < 4; nt++) {
                    mma16816(acc[mt][nt * 2],     af[mt], bfr[nt][0], bfr[nt][1]);
                    mma16816(acc[mt][nt * 2 + 1], af[mt], bfr[nt][2], bfr[nt][3]);
                }
        }
    }

    // epilogue: bias + store fp32 gates
    #pragma unroll
    for (int mt = 0; mt < 2; mt++) {
        int r = row0 + wm * 32 + mt * 16 + (lane >> 2);
        #pragma unroll
        for (int nt = 0; nt < 8; nt++) {
            int cl = wn * 64 + nt * 8 + (lane & 3) * 2;
            float b0 = s_bias[cl], b1 = s_bias[cl + 1];
            float2 v0 = make_float2(acc[mt][nt][0] + b0, acc[mt][nt][1] + b1);
            float2 v1 = make_float2(acc[mt][nt][2] + b0, acc[mt][nt][3] + b1);
            *(float2*)&g_gates[(size_t)r * GD + col0 + cl] = v0;
            *(float2*)&g_gates[(size_t)(r + 8) * GD + col0 + cl] = v1;
        }
    }
}

// ------------------- LSTM pointwise + trajectory update -------------------
__global__ void k_lstm(const float* __restrict__ W_out, const float* __restrict__ b_out,
                       const float* __restrict__ field_A, const float* __restrict__ trans,
                       float* __restrict__ pred) {
    int n = blockIdx.x, t = threadIdx.x;
    bool m = g_mask[n] != 0;
    __shared__ float r0[H], r1[H];
    __shared__ float pos_s[2];
    __shared__ float al_s[NK], z_s[NK];

    const float* g = &g_gates[(size_t)n * GD];
    float gi = g[t], gf = g[t + 128], gg = g[t + 256], go = g[t + 384];
    float c = g_c[(size_t)n * H + t];
    float h = g_h[(size_t)n * H + t];
    float cn = sigm(gf) * c + sigm(gi) * tanhf(gg);
    float hn = sigm(go) * tanhf(cn);
    float h2 = m ? hn : h;
    float c2 = m ? cn : c;
    g_h[(size_t)n * H + t] = h2;
    g_c[(size_t)n * H + t] = c2;

    if (t < NK) al_s[t] = g_alpha[(size_t)n * NK + t];
    r0[t] = h2 * W_out[2 * t];
    r1[t] = h2 * W_out[2 * t + 1];
    __syncthreads();
    for (int s = 64; s > 0; s >>= 1) {
        if (t < s) { r0[t] += r0[t + s]; r1[t] += r1[t + s]; }
        __syncthreads();
    }
    if (t < 2) {
        float out = (t == 0 ? r0[0] : r1[0]) + b_out[t];
        float rel = m ? out : g_rel[(size_t)n * 2 + t];
        float p = g_pos[(size_t)n * 2 + t] + rel;
        g_rel[(size_t)n * 2 + t] = rel;
        g_pos[(size_t)n * 2 + t] = p;
        pred[(size_t)n * 2 + t] = rel;
        pos_s[t] = p;
    }
    if (t < NK) {
        float z = 0.0f;
        #pragma unroll
        for (int k2 = 0; k2 < NK; k2++) z += al_s[k2] * trans[k2 * NK + t];
        z_s[t] = z;
    }
    __syncthreads();
    if (t < 2 * NK && m) {
        int k = t >> 1, e = t & 1;
        g_fd[(size_t)n * 2 * NK + t] =
            pos_s[0] * field_A[k * 4 + e] + pos_s[1] * field_A[k * 4 + 2 + e];
    }
    if (t < NK && m) {
        float mx = z_s[0];
        #pragma unroll
        for (int k = 1; k < NK; k++) mx = fmaxf(mx, z_s[k]);
        float s = 0.0f;
        #pragma unroll
        for (int k = 0; k < NK; k++) s += expf(z_s[k] - mx);
        g_alpha[(size_t)n * NK + t] = expf(z_s[t] - mx) / s;
    }
}

// ------------------- launch -------------------
extern "C" void kernel_launch(void* const* d_in, const int* in_sizes, int n_in,
                              void* d_out, int out_size) {
    const float* state_final = (const float*)d_in[0];
    const float* last_pos    = (const float*)d_in[1];
    const float* alpha0      = (const float*)d_in[2];
    const float* fields_disp0= (const float*)d_in[3];
    const float* W_pos       = (const float*)d_in[4];
    const float* b_pos       = (const float*)d_in[5];
    const float* W_fld       = (const float*)d_in[6];
    const float* b_fld       = (const float*)d_in[7];
    const float* W_pool      = (const float*)d_in[8];
    const float* b_pool      = (const float*)d_in[9];
    const float* Wx          = (const float*)d_in[10];
    const float* Wh          = (const float*)d_in[11];
    const float* b_lstm      = (const float*)d_in[12];
    const float* W_out       = (const float*)d_in[13];
    const float* b_out       = (const float*)d_in[14];
    const float* field_A     = (const float*)d_in[15];
    const float* trans       = (const float*)d_in[16];
    const int*   seg_ids     = (const int*)d_in[17];
    const unsigned char* seq_mask = (const unsigned char*)d_in[18];
    float* pred = (float*)d_out;   // (12, N, 2)

    static int attr_done = 0;
    if (!attr_done) {
        cudaFuncSetAttribute(k_gemm, cudaFuncAttributeMaxDynamicSharedMemorySize, GEMM_SMEM);
        cudaFuncSetAttribute(k_pool, cudaFuncAttributeMaxDynamicSharedMemorySize,
                             (H * H + 2 * H) * (int)sizeof(float));
        attr_done = 1;
    }

    k_mask_detect<<<1, 256>>>(seq_mask);
    k_mask_norm<<<(NROWS + 255) / 256, 256>>>(seq_mask);
    k_init_w<<<256, 256>>>(Wx, Wh, b_lstm);
    k_init_state<<<NROWS, 128>>>(state_final, last_pos, alpha0, fields_disp0,
                                 W_out, b_out, pred);

    for (int step = 1; step <= STEPS; step++) {
        k_seg_clear<<<(NSEG * H + 255) / 256, 256>>>();
        k_segmax<<<NROWS / SEG_R, H>>>(seg_ids);
        k_pool<<<NSEG / POOL_SEGS, 256, (H * H + 2 * H) * sizeof(float)>>>(W_pool, b_pool);
        k_x<<<NROWS / XROWS_PER_BLOCK, 128>>>(seg_ids, W_pos, b_pos, W_fld, b_fld);
        k_gemm<<<dim3(GD / 128, NROWS / 128), 256, GEMM_SMEM>>>();
        k_lstm<<<NROWS, H>>>(W_out, b_out, field_A, trans,
                             pred + (size_t)step * NROWS * 2);
    }
}

// round 6
// speedup vs baseline: 2.2404x; 1.2287x over previous
#include <cuda_runtime.h>
#include <cuda_bf16.h>
#include <cuda_fp16.h>
#include <cstdint>

#define NROWS 131072
#define H 128
#define NK 20
#define NSEG 8192
#define KIN 384          // 256 (x) + 128 (h)
#define GD 512           // 4*H gates
#define AW 768           // A row width: [hi(384) | lo(384)] fp16
#define STEPS 11
#define SROWS 8

// ------------------- persistent state (device globals; no allocs) -------------------
__device__ float    g_h     [(size_t)NROWS * H];
__device__ float    g_c     [(size_t)NROWS * H];
__device__ float    g_rel   [(size_t)NROWS * 2];
__device__ float    g_pos   [(size_t)NROWS * 2];
__device__ float    g_alpha [(size_t)NROWS * NK];
__device__ float    g_fd    [(size_t)NROWS * NK * 2];
__device__ unsigned g_segmax[(size_t)NSEG * H];
__device__ float    g_P     [(size_t)NSEG * H];
__device__ __half   g_xa    [(size_t)NROWS * AW];      // A: [hi(384) | lo(384)] fp16
__device__ __half   g_Wb    [(size_t)GD * KIN];        // B: [n][k] fp16, K-major
__device__ float    g_gates [(size_t)NROWS * GD];
__device__ float    g_bl    [GD];
__device__ unsigned char g_mask[NROWS];
__device__ int      g_fmt;

// ------------------- low-level helpers -------------------
__device__ __forceinline__ void cp16(uint32_t dst, const void* src) {
    asm volatile("cp.async.cg.shared.global [%0], [%1], 16;" :: "r"(dst), "l"(src));
}
#define CP_COMMIT() asm volatile("cp.async.commit_group;" ::: "memory")
#define CP_WAIT(n)  asm volatile("cp.async.wait_group %0;" :: "n"(n) : "memory")

__device__ __forceinline__ void ldm4(uint32_t* r, uint32_t addr) {
    asm volatile("ldmatrix.sync.aligned.m8n8.x4.shared.b16 {%0,%1,%2,%3}, [%4];"
                 : "=r"(r[0]), "=r"(r[1]), "=r"(r[2]), "=r"(r[3]) : "r"(addr));
}
__device__ __forceinline__ void mma16816(float* d, const uint32_t* a, uint32_t b0, uint32_t b1) {
    asm volatile("mma.sync.aligned.m16n8k16.row.col.f32.f16.f16.f32 "
                 "{%0,%1,%2,%3}, {%4,%5,%6,%7}, {%8,%9}, {%0,%1,%2,%3};"
                 : "+f"(d[0]), "+f"(d[1]), "+f"(d[2]), "+f"(d[3])
                 : "r"(a[0]), "r"(a[1]), "r"(a[2]), "r"(a[3]), "r"(b0), "r"(b1));
}

__device__ __forceinline__ unsigned enc_f(float f) {
    unsigned u = __float_as_uint(f);
    return (u & 0x80000000u) ? ~u : (u | 0x80000000u);
}
__device__ __forceinline__ float dec_f(unsigned u) {
    return (u & 0x80000000u) ? __uint_as_float(u & 0x7FFFFFFFu) : __uint_as_float(~u);
}
__device__ __forceinline__ float sigm(float x) { return 1.0f / (1.0f + expf(-x)); }

__device__ __forceinline__ void store_split(size_t n, int col, float v) {
    __half hi = __float2half_rn(v);
    g_xa[n * AW + col] = hi;
    g_xa[n * AW + 384 + col] = __float2half_rn(v - __half2float(hi));
}

// ------------------- mask format detect + normalize -------------------
__global__ void k_mask_detect(const unsigned char* __restrict__ raw) {
    __shared__ int cnt;
    if (threadIdx.x == 0) cnt = 0;
    __syncthreads();
    int local = 0;
    for (int i = threadIdx.x; i < 4096; i += 256)
        if ((i & 3) && raw[i]) local++;
    atomicAdd(&cnt, local);
    __syncthreads();
    if (threadIdx.x == 0) g_fmt = (cnt == 0) ? 1 : 0;
}
__global__ void k_mask_norm(const unsigned char* __restrict__ raw) {
    int n = blockIdx.x * blockDim.x + threadIdx.x;
    if (n < NROWS)
        g_mask[n] = g_fmt ? (raw[(size_t)4 * n] != 0) : (raw[n] != 0);
}

// ------------------- init: B fp16 [512 x 384] K-major + bias -------------------
__global__ void k_init_w(const float* __restrict__ Wx, const float* __restrict__ Wh,
                         const float* __restrict__ b_lstm) {
    int idx = blockIdx.x * blockDim.x + threadIdx.x;
    int tot = GD * KIN;
    for (int i = idx; i < tot; i += gridDim.x * blockDim.x) {
        int n = i / KIN, k = i % KIN;
        float w = (k < 256) ? Wx[(size_t)k * GD + n] : Wh[(size_t)(k - 256) * GD + n];
        g_Wb[(size_t)n * KIN + k] = __float2half_rn(w);
    }
    if (idx < GD) g_bl[idx] = b_lstm[idx];
}

// ------------------- init: per-row state + pred[0] -------------------
__global__ void k_init_state(const float* __restrict__ sf, const float* __restrict__ last_pos,
                             const float* __restrict__ a0, const float* __restrict__ fd0,
                             const float* __restrict__ W_out, const float* __restrict__ b_out,
                             float* __restrict__ pred0) {
    int n = blockIdx.x, t = threadIdx.x;
    __shared__ float r0[H], r1[H];
    __shared__ float av[NK];
    float hv = sf[(size_t)n * H + t];
    g_h[(size_t)n * H + t] = hv;
    g_c[(size_t)n * H + t] = 0.0f;
    r0[t] = hv * W_out[2 * t];
    r1[t] = hv * W_out[2 * t + 1];
    if (t < NK) av[t] = a0[(size_t)n * NK + t];
    __syncthreads();
    for (int s = 64; s > 0; s >>= 1) {
        if (t < s) { r0[t] += r0[t + s]; r1[t] += r1[t + s]; }
        __syncthreads();
    }
    if (t < 2) {
        float out = (t == 0 ? r0[0] : r1[0]) + b_out[t];
        g_rel[(size_t)n * 2 + t] = out;
        g_pos[(size_t)n * 2 + t] = last_pos[(size_t)n * 2 + t] + out;
        pred0[(size_t)n * 2 + t] = out;
    }
    if (t < NK) {
        float s = 0.0f;
        #pragma unroll
        for (int k = 0; k < NK; k++) s += av[k];
        g_alpha[(size_t)n * NK + t] = av[t] / s;
    }
    if (t < 2 * NK) g_fd[(size_t)n * 2 * NK + t] = fd0[(size_t)n * 2 * NK + t];
}

// ------------------- segment max (init path; per-step it lives in k_step) ------------
__global__ void k_seg_clear() {
    int i = blockIdx.x * blockDim.x + threadIdx.x;
    if (i < NSEG * H) g_segmax[i] = 0u;
}

#define SEG_R 16
__global__ void k_segmax_init(const int* __restrict__ seg_ids) {
    int t = threadIdx.x;
    int r0 = blockIdx.x * SEG_R;
    __shared__ int sid[SEG_R];
    if (t < SEG_R) sid[t] = seg_ids[r0 + t];
    __syncthreads();
    int cur = sid[0];
    unsigned mx = 0u;
    #pragma unroll
    for (int r = 0; r < SEG_R; r++) {
        int s = sid[r];
        if (s != cur) {
            atomicMax(&g_segmax[(size_t)cur * H + t], mx);
            cur = s; mx = 0u;
        }
        unsigned key = enc_f(g_h[(size_t)(r0 + r) * H + t]);
        mx = mx > key ? mx : key;
    }
    atomicMax(&g_segmax[(size_t)cur * H + t], mx);
}

// ------------------- init path: emb + h cols of A (once; per-step in k_step) ---------
__global__ void k_emb_init(const float* __restrict__ W_pos, const float* __restrict__ b_pos,
                           const float* __restrict__ W_fld, const float* __restrict__ b_fld) {
    __shared__ float Wf[NK * 2 * 64];
    __shared__ float Wp[2 * 64];
    __shared__ float bp[64], bf[64];
    __shared__ float dtp[NK * 2];
    int t = threadIdx.x;
    for (int i = t; i < NK * 2 * 64; i += 128) Wf[i] = W_fld[i];
    if (t < 128) Wp[t] = W_pos[t];
    if (t < 64)  { bp[t] = b_pos[t]; bf[t] = b_fld[t]; }
    int base = blockIdx.x * SROWS;
    for (int r = 0; r < SROWS; r++) {
        int n = base + r;
        __syncthreads();
        if (t < 2 * NK) dtp[t] = g_alpha[(size_t)n * NK + (t >> 1)] * g_fd[(size_t)n * 2 * NK + t];
        __syncthreads();
        float rx = g_rel[(size_t)n * 2 + 0];
        float ry = g_rel[(size_t)n * 2 + 1];
        float ev;
        if (t < 64) {
            ev = rx * Wp[t] + ry * Wp[64 + t] + bp[t];
        } else {
            int e = t - 64;
            float acc = bf[e];
            #pragma unroll
            for (int k = 0; k < 2 * NK; k++) acc += dtp[k] * Wf[k * 64 + e];
            ev = acc;
        }
        store_split((size_t)n, t, ev);
        store_split((size_t)n, 256 + t, g_h[(size_t)n * H + t]);
    }
}

// ------------------- per-step: pool GEMM over segments + gather into A ---------------
#define POOL_SEGS 32
__global__ void __launch_bounds__(256) k_pool(const float* __restrict__ W_pool,
                                              const float* __restrict__ b_pool) {
    extern __shared__ float psm[];           // [H*H] W_pool + [2*H] sv
    float* sv = psm + H * H;
    int t = threadIdx.x;
    for (int i = t; i < H * H; i += 256) psm[i] = W_pool[i];
    int s0 = blockIdx.x * POOL_SEGS;
    int half = t >> 7, col = t & 127;
    float b = b_pool[col];
    __syncthreads();
    for (int p = 0; p < POOL_SEGS; p += 2) {
        int s = s0 + p + half;
        sv[t] = dec_f(g_segmax[(size_t)s * H + col]);
        __syncthreads();
        float acc = b;
        #pragma unroll 8
        for (int k = 0; k < H; k++) acc += sv[half * H + k] * psm[k * H + col];
        g_P[(size_t)s * H + col] = fmaxf(acc, 0.0f);
        __syncthreads();
    }
}

__global__ void k_xpool(const int* __restrict__ seg_ids) {
    int t = threadIdx.x;
    int base = blockIdx.x * SROWS;
    #pragma unroll
    for (int r = 0; r < SROWS; r++) {
        int n = base + r;
        int s = seg_ids[n];
        store_split((size_t)n, 128 + t, g_P[(size_t)s * H + t]);
    }
}

// ------------------- mma.sync fp16 GEMM: gates = A x B^T + bias ----------------------
// CTA 128x128, 8 warps (4m x 2n), BK=32, 3-stage cp.async.
// 2 terms x 12 k-tiles: A_hi*B + A_lo*B  (A split fp16 pair, B single fp16).
#define NKT 24
#define SPAD 40    // 32 + 8 fp16 pad: 80B row stride, conflict-free ldmatrix
#define GSTAGES 3
#define GEMM_SMEM (2 * GSTAGES * 128 * SPAD * 2 + 512)

__global__ void __launch_bounds__(256) k_gemm() {
    extern __shared__ __half gsm[];
    __half (*As)[128][SPAD] = (__half (*)[128][SPAD])gsm;
    __half (*Bs)[128][SPAD] = (__half (*)[128][SPAD])(gsm + GSTAGES * 128 * SPAD);
    float* s_bias = (float*)(gsm + 2 * GSTAGES * 128 * SPAD);

    int t = threadIdx.x;
    int lane = t & 31, warp = t >> 5;
    int wm = warp & 3, wn = warp >> 2;
    int col0 = blockIdx.x * 128, row0 = blockIdx.y * 128;

    if (t < 128) s_bias[t] = g_bl[col0 + t];

    float acc[2][8][4];
    #pragma unroll
    for (int i = 0; i < 2; i++)
        #pragma unroll
        for (int j = 0; j < 8; j++)
            #pragma unroll
            for (int k = 0; k < 4; k++) acc[i][j][k] = 0.0f;

    int lr = t >> 2, lc = (t & 3) * 8;
    auto issue = [&](int it, int buf) {
        int term = it / 12, kt = it % 12;
        int acol = term * 384 + kt * 32 + lc;
        int bcol = kt * 32 + lc;
        #pragma unroll
        for (int i = 0; i < 2; i++) {
            int r = lr + i * 64;
            cp16((uint32_t)__cvta_generic_to_shared(&As[buf][r][lc]),
                 &g_xa[(size_t)(row0 + r) * AW + acol]);
            cp16((uint32_t)__cvta_generic_to_shared(&Bs[buf][r][lc]),
                 &g_Wb[(size_t)(col0 + r) * KIN + bcol]);
        }
        CP_COMMIT();
    };

    issue(0, 0);
    issue(1, 1);
    for (int it = 0; it < NKT; it++) {
        int buf = it % GSTAGES;
        CP_WAIT(1);
        __syncthreads();
        if (it + 2 < NKT) issue(it + 2, (it + 2) % GSTAGES);

        #pragma unroll
        for (int kh = 0; kh < 2; kh++) {
            uint32_t af[2][4];
            #pragma unroll
            for (int mt = 0; mt < 2; mt++) {
                int r = wm * 32 + mt * 16 + (lane & 15);
                int c = kh * 16 + (lane >> 4) * 8;
                ldm4(af[mt], (uint32_t)__cvta_generic_to_shared(&As[buf][r][c]));
            }
            uint32_t bfr[4][4];
            #pragma unroll
            for (int nt = 0; nt < 4; nt++) {
                int r = wn * 64 + nt * 16 + (lane & 7) + ((lane >> 4) & 1) * 8;
                int c = kh * 16 + ((lane >> 3) & 1) * 8;
                ldm4(bfr[nt], (uint32_t)__cvta_generic_to_shared(&Bs[buf][r][c]));
            }
            #pragma unroll
            for (int mt = 0; mt < 2; mt++)
                #pragma unroll
                for (int nt = 0; nt < 4; nt++) {
                    mma16816(acc[mt][nt * 2],     af[mt], bfr[nt][0], bfr[nt][1]);
                    mma16816(acc[mt][nt * 2 + 1], af[mt], bfr[nt][2], bfr[nt][3]);
                }
        }
    }

    #pragma unroll
    for (int mt = 0; mt < 2; mt++) {
        int r = row0 + wm * 32 + mt * 16 + (lane >> 2);
        #pragma unroll
        for (int nt = 0; nt < 8; nt++) {
            int cl = wn * 64 + nt * 8 + (lane & 3) * 2;
            float b0 = s_bias[cl], b1 = s_bias[cl + 1];
            float2 v0 = make_float2(acc[mt][nt][0] + b0, acc[mt][nt][1] + b1);
            float2 v1 = make_float2(acc[mt][nt][2] + b0, acc[mt][nt][3] + b1);
            *(float2*)&g_gates[(size_t)r * GD + col0 + cl] = v0;
            *(float2*)&g_gates[(size_t)(r + 8) * GD + col0 + cl] = v1;
        }
    }
}

// ------------- fused per-step: LSTM + out + traj + alpha/fd + A-write + segmax -------
__global__ void __launch_bounds__(128) k_step(
    const float* __restrict__ W_pos, const float* __restrict__ b_pos,
    const float* __restrict__ W_fld, const float* __restrict__ b_fld,
    const float* __restrict__ W_out, const float* __restrict__ b_out,
    const float* __restrict__ field_A, const float* __restrict__ trans,
    const int* __restrict__ seg_ids, float* __restrict__ pred)
{
    __shared__ float Wf[2 * NK * 64];
    __shared__ float Wp[128], bps[64], bfs[64];
    __shared__ float Wo[256], bo[2];
    __shared__ float tr_s[NK * NK];
    __shared__ float fA[NK * 4];
    __shared__ float red[8];
    __shared__ float al_s[NK], z_s[NK], dtp[2 * NK];
    __shared__ float rel_s[2], pos_s[2];
    __shared__ int sid[SROWS];

    int t = threadIdx.x;
    int lane = t & 31, warp = t >> 5;
    for (int i = t; i < 2 * NK * 64; i += 128) Wf[i] = W_fld[i];
    if (t < 128) Wp[t] = W_pos[t];
    if (t < 64) { bps[t] = b_pos[t]; bfs[t] = b_fld[t]; }
    for (int i = t; i < 256; i += 128) Wo[i] = W_out[i];
    if (t < 2) bo[t] = b_out[t];
    for (int i = t; i < NK * NK; i += 128) tr_s[i] = trans[i];
    if (t < NK * 4) fA[t] = field_A[t];
    int base = blockIdx.x * SROWS;
    if (t < SROWS) sid[t] = seg_ids[base + t];
    __syncthreads();

    int cur = sid[0];
    unsigned mx = 0u;

    for (int r = 0; r < SROWS; r++) {
        int n = base + r;
        bool m = g_mask[n] != 0;
        const float* g = &g_gates[(size_t)n * GD];
        float gi = g[t], gf = g[t + 128], gg = g[t + 256], go = g[t + 384];
        float c = g_c[(size_t)n * H + t];
        float h = g_h[(size_t)n * H + t];
        float cn = sigm(gf) * c + sigm(gi) * tanhf(gg);
        float hn = sigm(go) * tanhf(cn);
        float h2 = m ? hn : h;
        float c2 = m ? cn : c;
        g_h[(size_t)n * H + t] = h2;
        g_c[(size_t)n * H + t] = c2;
        store_split((size_t)n, 256 + t, h2);        // A: h cols for next step

        // batched segment max for next step
        int s = sid[r];
        if (s != cur) { atomicMax(&g_segmax[(size_t)cur * H + t], mx); cur = s; mx = 0u; }
        unsigned key = enc_f(h2);
        mx = mx > key ? mx : key;

        // out = h2 @ W_out (two dot-128 via warp shuffles)
        float p0 = h2 * Wo[2 * t], p1 = h2 * Wo[2 * t + 1];
        #pragma unroll
        for (int o = 16; o > 0; o >>= 1) {
            p0 += __shfl_down_sync(0xffffffffu, p0, o);
            p1 += __shfl_down_sync(0xffffffffu, p1, o);
        }
        if (lane == 0) { red[warp] = p0; red[4 + warp] = p1; }
        if (t < NK) al_s[t] = g_alpha[(size_t)n * NK + t];
        __syncthreads();

        if (t < NK) {
            float z = 0.0f;
            #pragma unroll
            for (int k2 = 0; k2 < NK; k2++) z += al_s[k2] * tr_s[k2 * NK + t];
            z_s[t] = z;
        }
        if (t < 2) {
            float out = red[4 * t] + red[4 * t + 1] + red[4 * t + 2] + red[4 * t + 3] + bo[t];
            float rel = m ? out : g_rel[(size_t)n * 2 + t];
            float p = g_pos[(size_t)n * 2 + t] + rel;
            g_rel[(size_t)n * 2 + t] = rel;
            g_pos[(size_t)n * 2 + t] = p;
            pred[(size_t)n * 2 + t] = rel;
            rel_s[t] = rel; pos_s[t] = p;
        }
        __syncthreads();

        if (t < 2 * NK) {
            int k = t >> 1, e = t & 1;
            float a2;
            if (m) {
                float mz = z_s[0];
                #pragma unroll
                for (int k2 = 1; k2 < NK; k2++) mz = fmaxf(mz, z_s[k2]);
                float ssum = 0.0f;
                #pragma unroll
                for (int k2 = 0; k2 < NK; k2++) ssum += expf(z_s[k2] - mz);
                a2 = expf(z_s[k] - mz) / ssum;
            } else {
                a2 = al_s[k];
            }
            float fdv = m ? (pos_s[0] * fA[k * 4 + e] + pos_s[1] * fA[k * 4 + 2 + e])
                          : g_fd[(size_t)n * 2 * NK + t];
            dtp[t] = fdv * a2;
            g_fd[(size_t)n * 2 * NK + t] = fdv;
            if (e == 0) g_alpha[(size_t)n * NK + k] = a2;
        }
        __syncthreads();

        float ev;
        if (t < 64) {
            ev = rel_s[0] * Wp[t] + rel_s[1] * Wp[64 + t] + bps[t];
        } else {
            int e = t - 64;
            float acc = bfs[e];
            #pragma unroll
            for (int k = 0; k < 2 * NK; k++) acc += dtp[k] * Wf[k * 64 + e];
            ev = acc;
        }
        store_split((size_t)n, t, ev);              // A: emb cols for next step
        __syncthreads();                            // protect smem reuse next row
    }
    atomicMax(&g_segmax[(size_t)cur * H + t], mx);
}

// ------------------- launch -------------------
extern "C" void kernel_launch(void* const* d_in, const int* in_sizes, int n_in,
                              void* d_out, int out_size) {
    const float* state_final = (const float*)d_in[0];
    const float* last_pos    = (const float*)d_in[1];
    const float* alpha0      = (const float*)d_in[2];
    const float* fields_disp0= (const float*)d_in[3];
    const float* W_pos       = (const float*)d_in[4];
    const float* b_pos       = (const float*)d_in[5];
    const float* W_fld       = (const float*)d_in[6];
    const float* b_fld       = (const float*)d_in[7];
    const float* W_pool      = (const float*)d_in[8];
    const float* b_pool      = (const float*)d_in[9];
    const float* Wx          = (const float*)d_in[10];
    const float* Wh          = (const float*)d_in[11];
    const float* b_lstm      = (const float*)d_in[12];
    const float* W_out       = (const float*)d_in[13];
    const float* b_out       = (const float*)d_in[14];
    const float* field_A     = (const float*)d_in[15];
    const float* trans       = (const float*)d_in[16];
    const int*   seg_ids     = (const int*)d_in[17];
    const unsigned char* seq_mask = (const unsigned char*)d_in[18];
    float* pred = (float*)d_out;   // (12, N, 2)

    static int attr_done = 0;
    if (!attr_done) {
        cudaFuncSetAttribute(k_gemm, cudaFuncAttributeMaxDynamicSharedMemorySize, GEMM_SMEM);
        cudaFuncSetAttribute(k_pool, cudaFuncAttributeMaxDynamicSharedMemorySize,
                             (H * H + 2 * H) * (int)sizeof(float));
        attr_done = 1;
    }

    k_mask_detect<<<1, 256>>>(seq_mask);
    k_mask_norm<<<(NROWS + 255) / 256, 256>>>(seq_mask);
    k_init_w<<<256, 256>>>(Wx, Wh, b_lstm);
    k_init_state<<<NROWS, 128>>>(state_final, last_pos, alpha0, fields_disp0,
                                 W_out, b_out, pred);
    k_seg_clear<<<(NSEG * H + 255) / 256, 256>>>();
    k_segmax_init<<<NROWS / SEG_R, H>>>(seg_ids);
    k_emb_init<<<NROWS / SROWS, 128>>>(W_pos, b_pos, W_fld, b_fld);

    for (int step = 1; step <= STEPS; step++) {
        k_pool<<<NSEG / POOL_SEGS, 256, (H * H + 2 * H) * sizeof(float)>>>(W_pool, b_pool);
        k_xpool<<<NROWS / SROWS, 128>>>(seg_ids);
        k_gemm<<<dim3(GD / 128, NROWS / 128), 256, GEMM_SMEM>>>();
        k_seg_clear<<<(NSEG * H + 255) / 256, 256>>>();
        k_step<<<NROWS / SROWS, 128>>>(W_pos, b_pos, W_fld, b_fld, W_out, b_out,
                                       field_A, trans, seg_ids,
                                       pred + (size_t)step * NROWS * 2);
    }
}

// round 7
// speedup vs baseline: 3.0226x; 1.3491x over previous
#include <cuda_runtime.h>
#include <cuda_bf16.h>
#include <cuda_fp16.h>
#include <cstdint>

#define NROWS 131072
#define H 128
#define NK 20
#define NSEG 8192
#define KIN 384          // 256 (x) + 128 (h)
#define GD 512           // 4*H gates
#define STEPS 11
#define SROWS 8

// ------------------- persistent state (device globals; no allocs) -------------------
__device__ float    g_h     [(size_t)NROWS * H];
__device__ float    g_c     [(size_t)NROWS * H];
__device__ float    g_rel   [(size_t)NROWS * 2];
__device__ float    g_pos   [(size_t)NROWS * 2];
__device__ float    g_alpha [(size_t)NROWS * NK];
__device__ float    g_fd    [(size_t)NROWS * NK * 2];
__device__ unsigned g_segmax[(size_t)NSEG * H];
__device__ float    g_P     [(size_t)NSEG * H];
__device__ __half   g_xa    [(size_t)NROWS * KIN];     // A fp16 [n][k]
__device__ __half   g_Wb    [(size_t)GD * KIN];        // B fp16 [n][k] K-major
__device__ float    g_gates [(size_t)NROWS * GD];
__device__ float    g_bl    [GD];
__device__ unsigned char g_mask[NROWS];
__device__ int      g_fmt;

// ------------------- low-level helpers -------------------
__device__ __forceinline__ void cp16(uint32_t dst, const void* src) {
    asm volatile("cp.async.cg.shared.global [%0], [%1], 16;" :: "r"(dst), "l"(src));
}
#define CP_COMMIT() asm volatile("cp.async.commit_group;" ::: "memory")
#define CP_WAIT(n)  asm volatile("cp.async.wait_group %0;" :: "n"(n) : "memory")

__device__ __forceinline__ void ldm4(uint32_t* r, uint32_t addr) {
    asm volatile("ldmatrix.sync.aligned.m8n8.x4.shared.b16 {%0,%1,%2,%3}, [%4];"
                 : "=r"(r[0]), "=r"(r[1]), "=r"(r[2]), "=r"(r[3]) : "r"(addr));
}
__device__ __forceinline__ void mma16816(float* d, const uint32_t* a, uint32_t b0, uint32_t b1) {
    asm volatile("mma.sync.aligned.m16n8k16.row.col.f32.f16.f16.f32 "
                 "{%0,%1,%2,%3}, {%4,%5,%6,%7}, {%8,%9}, {%0,%1,%2,%3};"
                 : "+f"(d[0]), "+f"(d[1]), "+f"(d[2]), "+f"(d[3])
                 : "r"(a[0]), "r"(a[1]), "r"(a[2]), "r"(a[3]), "r"(b0), "r"(b1));
}

__device__ __forceinline__ unsigned enc_f(float f) {
    unsigned u = __float_as_uint(f);
    return (u & 0x80000000u) ? ~u : (u | 0x80000000u);
}
__device__ __forceinline__ float dec_f(unsigned u) {
    return (u & 0x80000000u) ? __uint_as_float(u & 0x7FFFFFFFu) : __uint_as_float(~u);
}
__device__ __forceinline__ float sigm(float x) { return 1.0f / (1.0f + expf(-x)); }

__device__ __forceinline__ void store_a(size_t n, int col, float v) {
    g_xa[n * KIN + col] = __float2half_rn(v);
}

// ------------------- mask format detect + normalize -------------------
__global__ void k_mask_detect(const unsigned char* __restrict__ raw) {
    __shared__ int cnt;
    if (threadIdx.x == 0) cnt = 0;
    __syncthreads();
    int local = 0;
    for (int i = threadIdx.x; i < 4096; i += 256)
        if ((i & 3) && raw[i]) local++;
    atomicAdd(&cnt, local);
    __syncthreads();
    if (threadIdx.x == 0) g_fmt = (cnt == 0) ? 1 : 0;
}
__global__ void k_mask_norm(const unsigned char* __restrict__ raw) {
    int n = blockIdx.x * blockDim.x + threadIdx.x;
    if (n < NROWS)
        g_mask[n] = g_fmt ? (raw[(size_t)4 * n] != 0) : (raw[n] != 0);
}

// ------------------- init: B fp16 [512 x 384] K-major + bias -------------------
__global__ void k_init_w(const float* __restrict__ Wx, const float* __restrict__ Wh,
                         const float* __restrict__ b_lstm) {
    int idx = blockIdx.x * blockDim.x + threadIdx.x;
    int tot = GD * KIN;
    for (int i = idx; i < tot; i += gridDim.x * blockDim.x) {
        int n = i / KIN, k = i % KIN;
        float w = (k < 256) ? Wx[(size_t)k * GD + n] : Wh[(size_t)(k - 256) * GD + n];
        g_Wb[(size_t)n * KIN + k] = __float2half_rn(w);
    }
    if (idx < GD) g_bl[idx] = b_lstm[idx];
}

// ------------------- init: per-row state + pred[0] -------------------
__global__ void k_init_state(const float* __restrict__ sf, const float* __restrict__ last_pos,
                             const float* __restrict__ a0, const float* __restrict__ fd0,
                             const float* __restrict__ W_out, const float* __restrict__ b_out,
                             float* __restrict__ pred0) {
    int n = blockIdx.x, t = threadIdx.x;
    __shared__ float r0[H], r1[H];
    __shared__ float av[NK];
    float hv = sf[(size_t)n * H + t];
    g_h[(size_t)n * H + t] = hv;
    g_c[(size_t)n * H + t] = 0.0f;
    r0[t] = hv * W_out[2 * t];
    r1[t] = hv * W_out[2 * t + 1];
    if (t < NK) av[t] = a0[(size_t)n * NK + t];
    __syncthreads();
    for (int s = 64; s > 0; s >>= 1) {
        if (t < s) { r0[t] += r0[t + s]; r1[t] += r1[t + s]; }
        __syncthreads();
    }
    if (t < 2) {
        float out = (t == 0 ? r0[0] : r1[0]) + b_out[t];
        g_rel[(size_t)n * 2 + t] = out;
        g_pos[(size_t)n * 2 + t] = last_pos[(size_t)n * 2 + t] + out;
        pred0[(size_t)n * 2 + t] = out;
    }
    if (t < NK) {
        float s = 0.0f;
        #pragma unroll
        for (int k = 0; k < NK; k++) s += av[k];
        g_alpha[(size_t)n * NK + t] = av[t] / s;
    }
    if (t < 2 * NK) g_fd[(size_t)n * 2 * NK + t] = fd0[(size_t)n * 2 * NK + t];
}

// ------------------- segment max (init path; per-step it lives in k_step) ------------
__global__ void k_seg_clear() {
    int i = blockIdx.x * blockDim.x + threadIdx.x;
    if (i < NSEG * H) g_segmax[i] = 0u;
}

#define SEG_R 16
__global__ void k_segmax_init(const int* __restrict__ seg_ids) {
    int t = threadIdx.x;
    int r0 = blockIdx.x * SEG_R;
    __shared__ int sid[SEG_R];
    if (t < SEG_R) sid[t] = seg_ids[r0 + t];
    __syncthreads();
    int cur = sid[0];
    unsigned mx = 0u;
    #pragma unroll
    for (int r = 0; r < SEG_R; r++) {
        int s = sid[r];
        if (s != cur) {
            atomicMax(&g_segmax[(size_t)cur * H + t], mx);
            cur = s; mx = 0u;
        }
        unsigned key = enc_f(g_h[(size_t)(r0 + r) * H + t]);
        mx = mx > key ? mx : key;
    }
    atomicMax(&g_segmax[(size_t)cur * H + t], mx);
}

// ------------------- init path: emb + h cols of A (once; per-step in k_step) ---------
__global__ void k_emb_init(const float* __restrict__ W_pos, const float* __restrict__ b_pos,
                           const float* __restrict__ W_fld, const float* __restrict__ b_fld) {
    __shared__ float Wf[NK * 2 * 64];
    __shared__ float Wp[2 * 64];
    __shared__ float bp[64], bf[64];
    __shared__ float dtp[NK * 2];
    int t = threadIdx.x;
    for (int i = t; i < NK * 2 * 64; i += 128) Wf[i] = W_fld[i];
    if (t < 128) Wp[t] = W_pos[t];
    if (t < 64)  { bp[t] = b_pos[t]; bf[t] = b_fld[t]; }
    int base = blockIdx.x * SROWS;
    for (int r = 0; r < SROWS; r++) {
        int n = base + r;
        __syncthreads();
        if (t < 2 * NK) dtp[t] = g_alpha[(size_t)n * NK + (t >> 1)] * g_fd[(size_t)n * 2 * NK + t];
        __syncthreads();
        float rx = g_rel[(size_t)n * 2 + 0];
        float ry = g_rel[(size_t)n * 2 + 1];
        float ev;
        if (t < 64) {
            ev = rx * Wp[t] + ry * Wp[64 + t] + bp[t];
        } else {
            int e = t - 64;
            float acc = bf[e];
            #pragma unroll
            for (int k = 0; k < 2 * NK; k++) acc += dtp[k] * Wf[k * 64 + e];
            ev = acc;
        }
        store_a((size_t)n, t, ev);
        store_a((size_t)n, 256 + t, g_h[(size_t)n * H + t]);
    }
}

// ------------------- per-step: pool GEMM over segments + gather into A ---------------
#define POOL_SEGS 32
__global__ void __launch_bounds__(256) k_pool(const float* __restrict__ W_pool,
                                              const float* __restrict__ b_pool) {
    extern __shared__ float psm[];           // [H*H] W_pool + [2*H] sv
    float* sv = psm + H * H;
    int t = threadIdx.x;
    for (int i = t; i < H * H; i += 256) psm[i] = W_pool[i];
    int s0 = blockIdx.x * POOL_SEGS;
    int half = t >> 7, col = t & 127;
    float b = b_pool[col];
    __syncthreads();
    for (int p = 0; p < POOL_SEGS; p += 2) {
        int s = s0 + p + half;
        sv[t] = dec_f(g_segmax[(size_t)s * H + col]);
        __syncthreads();
        float acc = b;
        #pragma unroll 8
        for (int k = 0; k < H; k++) acc += sv[half * H + k] * psm[k * H + col];
        g_P[(size_t)s * H + col] = fmaxf(acc, 0.0f);
        __syncthreads();
    }
}

__global__ void k_xpool(const int* __restrict__ seg_ids) {
    int t = threadIdx.x;
    int base = blockIdx.x * SROWS;
    #pragma unroll
    for (int r = 0; r < SROWS; r++) {
        int n = base + r;
        int s = seg_ids[n];
        store_a((size_t)n, 128 + t, g_P[(size_t)s * H + t]);
    }
}

// ------------------- mma.sync fp16 GEMM: gates = A x B^T + bias ----------------------
// CTA 128x128, 8 warps (4m x 2n), BK=32, 3-stage cp.async, 12 k-tiles.
#define NKT 12
#define SPAD 40    // 32 + 8 fp16 pad: 80B row stride, conflict-free ldmatrix
#define GSTAGES 3
#define GEMM_SMEM (2 * GSTAGES * 128 * SPAD * 2 + 512)

__global__ void __launch_bounds__(256) k_gemm() {
    extern __shared__ __half gsm[];
    __half (*As)[128][SPAD] = (__half (*)[128][SPAD])gsm;
    __half (*Bs)[128][SPAD] = (__half (*)[128][SPAD])(gsm + GSTAGES * 128 * SPAD);
    float* s_bias = (float*)(gsm + 2 * GSTAGES * 128 * SPAD);

    int t = threadIdx.x;
    int lane = t & 31, warp = t >> 5;
    int wm = warp & 3, wn = warp >> 2;
    int col0 = blockIdx.x * 128, row0 = blockIdx.y * 128;

    if (t < 128) s_bias[t] = g_bl[col0 + t];

    float acc[2][8][4];
    #pragma unroll
    for (int i = 0; i < 2; i++)
        #pragma unroll
        for (int j = 0; j < 8; j++)
            #pragma unroll
            for (int k = 0; k < 4; k++) acc[i][j][k] = 0.0f;

    int lr = t >> 2, lc = (t & 3) * 8;
    auto issue = [&](int it, int buf) {
        int col = it * 32 + lc;
        #pragma unroll
        for (int i = 0; i < 2; i++) {
            int r = lr + i * 64;
            cp16((uint32_t)__cvta_generic_to_shared(&As[buf][r][lc]),
                 &g_xa[(size_t)(row0 + r) * KIN + col]);
            cp16((uint32_t)__cvta_generic_to_shared(&Bs[buf][r][lc]),
                 &g_Wb[(size_t)(col0 + r) * KIN + col]);
        }
        CP_COMMIT();
    };

    issue(0, 0);
    issue(1, 1);
    for (int it = 0; it < NKT; it++) {
        int buf = it % GSTAGES;
        CP_WAIT(1);
        __syncthreads();
        if (it + 2 < NKT) issue(it + 2, (it + 2) % GSTAGES);

        #pragma unroll
        for (int kh = 0; kh < 2; kh++) {
            uint32_t af[2][4];
            #pragma unroll
            for (int mt = 0; mt < 2; mt++) {
                int r = wm * 32 + mt * 16 + (lane & 15);
                int c = kh * 16 + (lane >> 4) * 8;
                ldm4(af[mt], (uint32_t)__cvta_generic_to_shared(&As[buf][r][c]));
            }
            uint32_t bfr[4][4];
            #pragma unroll
            for (int nt = 0; nt < 4; nt++) {
                int r = wn * 64 + nt * 16 + (lane & 7) + ((lane >> 4) & 1) * 8;
                int c = kh * 16 + ((lane >> 3) & 1) * 8;
                ldm4(bfr[nt], (uint32_t)__cvta_generic_to_shared(&Bs[buf][r][c]));
            }
            #pragma unroll
            for (int mt = 0; mt < 2; mt++)
                #pragma unroll
                for (int nt = 0; nt < 4; nt++) {
                    mma16816(acc[mt][nt * 2],     af[mt], bfr[nt][0], bfr[nt][1]);
                    mma16816(acc[mt][nt * 2 + 1], af[mt], bfr[nt][2], bfr[nt][3]);
                }
        }
    }

    #pragma unroll
    for (int mt = 0; mt < 2; mt++) {
        int r = row0 + wm * 32 + mt * 16 + (lane >> 2);
        #pragma unroll
        for (int nt = 0; nt < 8; nt++) {
            int cl = wn * 64 + nt * 8 + (lane & 3) * 2;
            float b0 = s_bias[cl], b1 = s_bias[cl + 1];
            float2 v0 = make_float2(acc[mt][nt][0] + b0, acc[mt][nt][1] + b1);
            float2 v1 = make_float2(acc[mt][nt][2] + b0, acc[mt][nt][3] + b1);
            *(float2*)&g_gates[(size_t)r * GD + col0 + cl] = v0;
            *(float2*)&g_gates[(size_t)(r + 8) * GD + col0 + cl] = v1;
        }
    }
}

// ------------- fused per-step: LSTM + out + traj + alpha/fd + A-write + segmax -------
__global__ void __launch_bounds__(128) k_step(
    const float* __restrict__ W_pos, const float* __restrict__ b_pos,
    const float* __restrict__ W_fld, const float* __restrict__ b_fld,
    const float* __restrict__ W_out, const float* __restrict__ b_out,
    const float* __restrict__ field_A, const float* __restrict__ trans,
    const int* __restrict__ seg_ids, float* __restrict__ pred)
{
    __shared__ float Wf[2 * NK * 64];
    __shared__ float Wp[128], bps[64], bfs[64];
    __shared__ float Wo[256], bo[2];
    __shared__ float tr_s[NK * NK];
    __shared__ float fA[NK * 4];
    __shared__ float red[8];
    __shared__ float al_s[NK], z_s[NK], dtp[2 * NK];
    __shared__ float rel_s[2], pos_s[2];
    __shared__ int sid[SROWS];

    int t = threadIdx.x;
    int lane = t & 31, warp = t >> 5;
    for (int i = t; i < 2 * NK * 64; i += 128) Wf[i] = W_fld[i];
    if (t < 128) Wp[t] = W_pos[t];
    if (t < 64) { bps[t] = b_pos[t]; bfs[t] = b_fld[t]; }
    for (int i = t; i < 256; i += 128) Wo[i] = W_out[i];
    if (t < 2) bo[t] = b_out[t];
    for (int i = t; i < NK * NK; i += 128) tr_s[i] = trans[i];
    if (t < NK * 4) fA[t] = field_A[t];
    int base = blockIdx.x * SROWS;
    if (t < SROWS) sid[t] = seg_ids[base + t];
    __syncthreads();

    int cur = sid[0];
    unsigned mx = 0u;

    for (int r = 0; r < SROWS; r++) {
        int n = base + r;
        bool m = g_mask[n] != 0;
        const float* g = &g_gates[(size_t)n * GD];
        float gi = g[t], gf = g[t + 128], gg = g[t + 256], go = g[t + 384];
        float c = g_c[(size_t)n * H + t];
        float h = g_h[(size_t)n * H + t];
        float cn = sigm(gf) * c + sigm(gi) * tanhf(gg);
        float hn = sigm(go) * tanhf(cn);
        float h2 = m ? hn : h;
        float c2 = m ? cn : c;
        g_h[(size_t)n * H + t] = h2;
        g_c[(size_t)n * H + t] = c2;
        store_a((size_t)n, 256 + t, h2);            // A: h cols for next step

        // batched segment max for next step
        int s = sid[r];
        if (s != cur) { atomicMax(&g_segmax[(size_t)cur * H + t], mx); cur = s; mx = 0u; }
        unsigned key = enc_f(h2);
        mx = mx > key ? mx : key;

        // out = h2 @ W_out (two dot-128 via warp shuffles)
        float p0 = h2 * Wo[2 * t], p1 = h2 * Wo[2 * t + 1];
        #pragma unroll
        for (int o = 16; o > 0; o >>= 1) {
            p0 += __shfl_down_sync(0xffffffffu, p0, o);
            p1 += __shfl_down_sync(0xffffffffu, p1, o);
        }
        if (lane == 0) { red[warp] = p0; red[4 + warp] = p1; }
        if (t < NK) al_s[t] = g_alpha[(size_t)n * NK + t];
        __syncthreads();

        if (t < NK) {
            float z = 0.0f;
            #pragma unroll
            for (int k2 = 0; k2 < NK; k2++) z += al_s[k2] * tr_s[k2 * NK + t];
            z_s[t] = z;
        }
        if (t < 2) {
            float out = red[4 * t] + red[4 * t + 1] + red[4 * t + 2] + red[4 * t + 3] + bo[t];
            float rel = m ? out : g_rel[(size_t)n * 2 + t];
            float p = g_pos[(size_t)n * 2 + t] + rel;
            g_rel[(size_t)n * 2 + t] = rel;
            g_pos[(size_t)n * 2 + t] = p;
            pred[(size_t)n * 2 + t] = rel;
            rel_s[t] = rel; pos_s[t] = p;
        }
        __syncthreads();

        if (t < 2 * NK) {
            int k = t >> 1, e = t & 1;
            float a2;
            if (m) {
                float mz = z_s[0];
                #pragma unroll
                for (int k2 = 1; k2 < NK; k2++) mz = fmaxf(mz, z_s[k2]);
                float ssum = 0.0f;
                #pragma unroll
                for (int k2 = 0; k2 < NK; k2++) ssum += expf(z_s[k2] - mz);
                a2 = expf(z_s[k] - mz) / ssum;
            } else {
                a2 = al_s[k];
            }
            float fdv = m ? (pos_s[0] * fA[k * 4 + e] + pos_s[1] * fA[k * 4 + 2 + e])
                          : g_fd[(size_t)n * 2 * NK + t];
            dtp[t] = fdv * a2;
            g_fd[(size_t)n * 2 * NK + t] = fdv;
            if (e == 0) g_alpha[(size_t)n * NK + k] = a2;
        }
        __syncthreads();

        float ev;
        if (t < 64) {
            ev = rel_s[0] * Wp[t] + rel_s[1] * Wp[64 + t] + bps[t];
        } else {
            int e = t - 64;
            float acc = bfs[e];
            #pragma unroll
            for (int k = 0; k < 2 * NK; k++) acc += dtp[k] * Wf[k * 64 + e];
            ev = acc;
        }
        store_a((size_t)n, t, ev);                  // A: emb cols for next step
        __syncthreads();                            // protect smem reuse next row
    }
    atomicMax(&g_segmax[(size_t)cur * H + t], mx);
}

// ------------------- launch -------------------
extern "C" void kernel_launch(void* const* d_in, const int* in_sizes, int n_in,
                              void* d_out, int out_size) {
    const float* state_final = (const float*)d_in[0];
    const float* last_pos    = (const float*)d_in[1];
    const float* alpha0      = (const float*)d_in[2];
    const float* fields_disp0= (const float*)d_in[3];
    const float* W_pos       = (const float*)d_in[4];
    const float* b_pos       = (const float*)d_in[5];
    const float* W_fld       = (const float*)d_in[6];
    const float* b_fld       = (const float*)d_in[7];
    const float* W_pool      = (const float*)d_in[8];
    const float* b_pool      = (const float*)d_in[9];
    const float* Wx          = (const float*)d_in[10];
    const float* Wh          = (const float*)d_in[11];
    const float* b_lstm      = (const float*)d_in[12];
    const float* W_out       = (const float*)d_in[13];
    const float* b_out       = (const float*)d_in[14];
    const float* field_A     = (const float*)d_in[15];
    const float* trans       = (const float*)d_in[16];
    const int*   seg_ids     = (const int*)d_in[17];
    const unsigned char* seq_mask = (const unsigned char*)d_in[18];
    float* pred = (float*)d_out;   // (12, N, 2)

    static int attr_done = 0;
    if (!attr_done) {
        cudaFuncSetAttribute(k_gemm, cudaFuncAttributeMaxDynamicSharedMemorySize, GEMM_SMEM);
        cudaFuncSetAttribute(k_pool, cudaFuncAttributeMaxDynamicSharedMemorySize,
                             (H * H + 2 * H) * (int)sizeof(float));
        attr_done = 1;
    }

    k_mask_detect<<<1, 256>>>(seq_mask);
    k_mask_norm<<<(NROWS + 255) / 256, 256>>>(seq_mask);
    k_init_w<<<256, 256>>>(Wx, Wh, b_lstm);
    k_init_state<<<NROWS, 128>>>(state_final, last_pos, alpha0, fields_disp0,
                                 W_out, b_out, pred);
    k_seg_clear<<<(NSEG * H + 255) / 256, 256>>>();
    k_segmax_init<<<NROWS / SEG_R, H>>>(seg_ids);
    k_emb_init<<<NROWS / SROWS, 128>>>(W_pos, b_pos, W_fld, b_fld);

    for (int step = 1; step <= STEPS; step++) {
        k_pool<<<NSEG / POOL_SEGS, 256, (H * H + 2 * H) * sizeof(float)>>>(W_pool, b_pool);
        k_xpool<<<NROWS / SROWS, 128>>>(seg_ids);
        k_gemm<<<dim3(GD / 128, NROWS / 128), 256, GEMM_SMEM>>>();
        k_seg_clear<<<(NSEG * H + 255) / 256, 256>>>();
        k_step<<<NROWS / SROWS, 128>>>(W_pos, b_pos, W_fld, b_fld, W_out, b_out,
                                       field_A, trans, seg_ids,
                                       pred + (size_t)step * NROWS * 2);
    }
}